// round 1
// baseline (speedup 1.0000x reference)
#include <cuda_runtime.h>
#include <cuda_bf16.h>
#include <cstddef>

// Problem constants
#define BATCH 64
#define N1 1024
#define N2 512
#define DMODEL 256
#define F0K 512
#define F1K 384

// ---------------------------------------------------------------------------
// Scratch (no allocations allowed -> __device__ globals)
// ---------------------------------------------------------------------------
__device__ float g_h0[(size_t)BATCH * N1 * DMODEL];   // 64 MB
__device__ float g_h1[(size_t)BATCH * N2 * DMODEL];   // 32 MB
__device__ float g_eA[BATCH * N1];   // h0 . a1_0  (rows for o00/o01)
__device__ float g_eB[BATCH * N1];   // h0 . a2_0  (cols for o00)
__device__ float g_eC[BATCH * N2];   // h1 . a2_0  (cols for o01)
__device__ float g_eD[BATCH * N2];   // h1 . a1_1  (rows for o10/o11)
__device__ float g_eE[BATCH * N1];   // h0 . a2_1  (cols for o10)
__device__ float g_eF[BATCH * N2];   // h1 . a2_1  (cols for o11)
__device__ float g_mx[4 * BATCH];    // per-batch max of e2 for each block

// ---------------------------------------------------------------------------
// GEMM: C[rows,256] = A[rows,K] @ W[K,256]
// BM=128, BN=64, BK=16, 256 threads, 8x4 micro-tile
// ---------------------------------------------------------------------------
__global__ __launch_bounds__(256) void gemm256(
    const float* __restrict__ A, const float* __restrict__ W,
    float* __restrict__ C, int rows, int K)
{
    __shared__ __align__(16) float As[16][128];   // transposed A tile
    __shared__ __align__(16) float Bs[16][64];

    const int t   = threadIdx.x;
    const int m0  = blockIdx.x * 128;
    const int nc0 = blockIdx.y * 64;
    const int tx  = t & 15;          // col group -> cols nc0 + tx*4 .. +3
    const int ty  = t >> 4;          // row group -> rows m0 + ty*8 .. +7

    const int arow = t >> 1;
    const int akq  = (t & 1) * 8;
    const int brow = t >> 4;
    const int bcol = (t & 15) * 4;

    const float* Ap = A + (size_t)(m0 + arow) * K + akq;
    const float* Wp = W + (size_t)brow * 256 + nc0 + bcol;

    float acc[8][4];
#pragma unroll
    for (int i = 0; i < 8; ++i)
#pragma unroll
        for (int j = 0; j < 4; ++j) acc[i][j] = 0.f;

    for (int k0 = 0; k0 < K; k0 += 16) {
        float4 a0 = *(const float4*)(Ap + k0);
        float4 a1 = *(const float4*)(Ap + k0 + 4);
        float4 bv = *(const float4*)(Wp + (size_t)k0 * 256);
        __syncthreads();
        As[akq + 0][arow] = a0.x; As[akq + 1][arow] = a0.y;
        As[akq + 2][arow] = a0.z; As[akq + 3][arow] = a0.w;
        As[akq + 4][arow] = a1.x; As[akq + 5][arow] = a1.y;
        As[akq + 6][arow] = a1.z; As[akq + 7][arow] = a1.w;
        *(float4*)&Bs[brow][bcol] = bv;
        __syncthreads();
#pragma unroll
        for (int kk = 0; kk < 16; ++kk) {
            float4 av0 = *(const float4*)&As[kk][ty * 8];
            float4 av1 = *(const float4*)&As[kk][ty * 8 + 4];
            float4 b2  = *(const float4*)&Bs[kk][tx * 4];
            float ar[8] = {av0.x, av0.y, av0.z, av0.w, av1.x, av1.y, av1.z, av1.w};
#pragma unroll
            for (int i = 0; i < 8; ++i) {
                acc[i][0] += ar[i] * b2.x;
                acc[i][1] += ar[i] * b2.y;
                acc[i][2] += ar[i] * b2.z;
                acc[i][3] += ar[i] * b2.w;
            }
        }
    }
#pragma unroll
    for (int i = 0; i < 8; ++i) {
        float4 o = make_float4(acc[i][0], acc[i][1], acc[i][2], acc[i][3]);
        *(float4*)(C + (size_t)(m0 + ty * 8 + i) * 256 + nc0 + tx * 4) = o;
    }
}

// ---------------------------------------------------------------------------
// e = h @ a   (per-row dot of length 256). One warp per row.
// ---------------------------------------------------------------------------
__global__ __launch_bounds__(256) void edot_kernel(
    const float* __restrict__ h, const float* __restrict__ a,
    float* __restrict__ e, int rows)
{
    const int r = blockIdx.x * 8 + (threadIdx.x >> 5);
    const int lane = threadIdx.x & 31;
    const float* hr = h + (size_t)r * 256;
    float s = 0.f;
#pragma unroll
    for (int i = 0; i < 8; ++i) s += hr[lane + i * 32] * a[lane + i * 32];
#pragma unroll
    for (int o = 16; o > 0; o >>= 1) s += __shfl_xor_sync(0xffffffffu, s, o);
    if (lane == 0) e[r] = s;
}

// Per-batch max of e2 (for the monotone-leakyrelu softmax shift bound)
__global__ __launch_bounds__(256) void bmax_kernel(
    const float* __restrict__ e2, float* __restrict__ mx, int M)
{
    __shared__ float red[256];
    const int b = blockIdx.x;
    const int t = threadIdx.x;
    const float* p = e2 + (size_t)b * M;
    float m = -3.4e38f;
    for (int i = t; i < M; i += 256) m = fmaxf(m, p[i]);
    red[t] = m;
    __syncthreads();
    for (int s = 128; s > 0; s >>= 1) {
        if (t < s) red[t] = fmaxf(red[t], red[t + s]);
        __syncthreads();
    }
    if (t == 0) mx[b] = red[0];
}

// ---------------------------------------------------------------------------
// Fused masked attention: out[n,:] = (deg/sumw) * sum_m w[n,m]*g[m,:] + bias
// w[n,m] = adj[n,m]>0 ? exp(lrelu(e1[n]+e2[m]) - shift[n]) : 0
// shift[n] = lrelu(e1[n] + max_b e2)  >= all scores in the row (monotone lrelu)
// Single pass over adj, flash-style; 64 rows x 256 cols per CTA, BK=32.
// ---------------------------------------------------------------------------
__global__ __launch_bounds__(256, 2) void att_kernel(
    const float* __restrict__ g, const int* __restrict__ adj,
    const float* __restrict__ e1, const float* __restrict__ e2,
    const float* __restrict__ maxe2, const float* __restrict__ bias,
    float* __restrict__ out, int N, int M)
{
    __shared__ __align__(16) float gs[32][256];   // 32 KB g tile
    __shared__ float ws[64][33];                  // padded w tile
    __shared__ float e1s[64], shifts[64], sumw[64], degw[64];

    const int b    = blockIdx.y;
    const int n0   = blockIdx.x * 64;
    const int t    = threadIdx.x;
    const int lane = t & 31;
    const int warp = t >> 5;

    if (t < 64) {
        float v = e1[(size_t)b * N + n0 + t];
        e1s[t] = v;
        float s = v + maxe2[b];
        shifts[t] = fmaxf(s, 0.2f * s);
        sumw[t] = 0.f;
        degw[t] = 0.f;
    }

    float acc[8][8];
#pragma unroll
    for (int i = 0; i < 8; ++i)
#pragma unroll
        for (int j = 0; j < 8; ++j) acc[i][j] = 0.f;

    const float4* gb4  = (const float4*)(g + (size_t)b * M * 256);
    const int*    adjb = adj + (size_t)b * N * M + (size_t)n0 * M;
    const float*  e2b  = e2 + (size_t)b * M;
    float4* gs4 = (float4*)&gs[0][0];   // [32][64] float4 view

    __syncthreads();

    for (int m0 = 0; m0 < M; m0 += 32) {
        float e2v = e2b[m0 + lane];
        __syncthreads();   // previous tile's compute done before overwrite
        // load g tile (32 x 256 f32 = 2048 float4, 8 per thread, coalesced)
#pragma unroll
        for (int j = 0; j < 8; ++j) {
            int f = t + j * 256;
            int row = f >> 6;
            int col = f & 63;
            gs4[row * 64 + col] = gb4[(size_t)(m0 + row) * 64 + col];
        }
        // compute w tile: warp handles rows {warp, warp+8, ..., warp+56}, lane = m
#pragma unroll
        for (int k = 0; k < 8; ++k) {
            int r = warp + 8 * k;
            int a = adjb[(size_t)r * M + m0 + lane];
            float val = e1s[r] + e2v;
            float l = fmaxf(val, 0.2f * val);   // leaky_relu(0.2)
            float w = (a > 0) ? __expf(l - shifts[r]) : 0.f;
            ws[r][lane] = w;
            float s = w;
#pragma unroll
            for (int o = 16; o > 0; o >>= 1) s += __shfl_xor_sync(0xffffffffu, s, o);
            unsigned bal = __ballot_sync(0xffffffffu, a > 0);
            if (lane == 0) { sumw[r] += s; degw[r] += (float)__popc(bal); }
        }
        __syncthreads();
        // FMA phase: thread owns rows warp*8..+7, cols lane*4 and 128+lane*4
#pragma unroll
        for (int kk = 0; kk < 32; ++kk) {
            float wr[8];
#pragma unroll
            for (int i = 0; i < 8; ++i) wr[i] = ws[warp * 8 + i][kk];
            float4 b0 = gs4[kk * 64 + lane];
            float4 b1 = gs4[kk * 64 + 32 + lane];
#pragma unroll
            for (int i = 0; i < 8; ++i) {
                acc[i][0] += wr[i] * b0.x; acc[i][1] += wr[i] * b0.y;
                acc[i][2] += wr[i] * b0.z; acc[i][3] += wr[i] * b0.w;
                acc[i][4] += wr[i] * b1.x; acc[i][5] += wr[i] * b1.y;
                acc[i][6] += wr[i] * b1.z; acc[i][7] += wr[i] * b1.w;
            }
        }
    }
    __syncthreads();

    float4 bi0 = ((const float4*)bias)[lane];
    float4 bi1 = ((const float4*)bias)[32 + lane];
#pragma unroll
    for (int i = 0; i < 8; ++i) {
        int r = warp * 8 + i;
        float dg = degw[r];
        float scale = (dg > 0.f) ? dg / sumw[r] : 0.f;   // deg==0 -> out = bias
        float4 o0, o1;
        o0.x = acc[i][0] * scale + bi0.x;
        o0.y = acc[i][1] * scale + bi0.y;
        o0.z = acc[i][2] * scale + bi0.z;
        o0.w = acc[i][3] * scale + bi0.w;
        o1.x = acc[i][4] * scale + bi1.x;
        o1.y = acc[i][5] * scale + bi1.y;
        o1.z = acc[i][6] * scale + bi1.z;
        o1.w = acc[i][7] * scale + bi1.w;
        float4* op = (float4*)(out + ((size_t)b * N + n0 + r) * 256);
        op[lane]      = o0;
        op[32 + lane] = o1;
    }
}

// ---------------------------------------------------------------------------
// Launch
// ---------------------------------------------------------------------------
extern "C" void kernel_launch(void* const* d_in, const int* in_sizes, int n_in,
                              void* d_out, int out_size)
{
    const float* x0   = (const float*)d_in[0];
    const float* x1   = (const float*)d_in[1];
    const float* W0   = (const float*)d_in[2];
    const float* W1   = (const float*)d_in[3];
    const float* a1_0 = (const float*)d_in[4];
    const float* a2_0 = (const float*)d_in[5];
    const float* a1_1 = (const float*)d_in[6];
    const float* a2_1 = (const float*)d_in[7];
    const float* bias = (const float*)d_in[8];
    const int* adj00  = (const int*)d_in[9];
    const int* adj01  = (const int*)d_in[10];
    const int* adj10  = (const int*)d_in[11];
    const int* adj11  = (const int*)d_in[12];
    float* out = (float*)d_out;

    float *h0, *h1, *eA, *eB, *eC, *eD, *eE, *eF, *mx;
    cudaGetSymbolAddress((void**)&h0, g_h0);
    cudaGetSymbolAddress((void**)&h1, g_h1);
    cudaGetSymbolAddress((void**)&eA, g_eA);
    cudaGetSymbolAddress((void**)&eB, g_eB);
    cudaGetSymbolAddress((void**)&eC, g_eC);
    cudaGetSymbolAddress((void**)&eD, g_eD);
    cudaGetSymbolAddress((void**)&eE, g_eE);
    cudaGetSymbolAddress((void**)&eF, g_eF);
    cudaGetSymbolAddress((void**)&mx, g_mx);

    const int R0 = BATCH * N1;   // 65536
    const int R1 = BATCH * N2;   // 32768

    // h = x @ W
    gemm256<<<dim3(R0 / 128, 4), 256>>>(x0, W0, h0, R0, F0K);
    gemm256<<<dim3(R1 / 128, 4), 256>>>(x1, W1, h1, R1, F1K);

    // attention logit vectors
    edot_kernel<<<R0 / 8, 256>>>(h0, a1_0, eA, R0);
    edot_kernel<<<R0 / 8, 256>>>(h0, a2_0, eB, R0);
    edot_kernel<<<R1 / 8, 256>>>(h1, a2_0, eC, R1);
    edot_kernel<<<R1 / 8, 256>>>(h1, a1_1, eD, R1);
    edot_kernel<<<R0 / 8, 256>>>(h0, a2_1, eE, R0);
    edot_kernel<<<R1 / 8, 256>>>(h1, a2_1, eF, R1);

    // per-batch e2 maxima (softmax shift bounds)
    bmax_kernel<<<BATCH, 256>>>(eB, mx + 0 * BATCH, N1);
    bmax_kernel<<<BATCH, 256>>>(eC, mx + 1 * BATCH, N2);
    bmax_kernel<<<BATCH, 256>>>(eE, mx + 2 * BATCH, N1);
    bmax_kernel<<<BATCH, 256>>>(eF, mx + 3 * BATCH, N2);

    // four fused attention blocks; output layout: o00 | o01 | o10 | o11
    float* o00 = out;
    float* o01 = out + (size_t)BATCH * N1 * DMODEL;
    float* o10 = o01 + (size_t)BATCH * N1 * DMODEL;
    float* o11 = o10 + (size_t)BATCH * N2 * DMODEL;

    att_kernel<<<dim3(N1 / 64, BATCH), 256>>>(h0, adj00, eA, eB, mx + 0 * BATCH, bias, o00, N1, N1);
    att_kernel<<<dim3(N1 / 64, BATCH), 256>>>(h1, adj01, eA, eC, mx + 1 * BATCH, bias, o01, N1, N2);
    att_kernel<<<dim3(N2 / 64, BATCH), 256>>>(h0, adj10, eD, eE, mx + 2 * BATCH, bias, o10, N2, N1);
    att_kernel<<<dim3(N2 / 64, BATCH), 256>>>(h1, adj11, eD, eF, mx + 3 * BATCH, bias, o11, N2, N2);
}

// round 5
// speedup vs baseline: 1.6976x; 1.6976x over previous
#include <cuda_runtime.h>
#include <cuda_fp16.h>
#include <cstdint>
#include <cstddef>

#define BATCH 64
#define N1 1024
#define N2 512
#define F0K 512
#define F1K 384

// ---------------------------------------------------------------------------
// Scratch
// ---------------------------------------------------------------------------
__device__ __half g_h0hi[(size_t)BATCH * N1 * 256];
__device__ __half g_h0lo[(size_t)BATCH * N1 * 256];
__device__ __half g_h1hi[(size_t)BATCH * N2 * 256];
__device__ __half g_h1lo[(size_t)BATCH * N2 * 256];
__device__ float g_eA[BATCH * N1];
__device__ float g_eB[BATCH * N1];
__device__ float g_eC[BATCH * N2];
__device__ float g_eD[BATCH * N2];
__device__ float g_eE[BATCH * N1];
__device__ float g_eF[BATCH * N2];
__device__ float g_mx[4 * BATCH];
__device__ float g_P2[2 * BATCH * (N1 + N2)];
__device__ float g_Q2[2 * BATCH * (N1 + N2)];

// ---------------------------------------------------------------------------
// mma.sync / ldmatrix helpers (sm_80 PTX, valid at base sm_103 target)
// ---------------------------------------------------------------------------
__device__ __forceinline__ void ldsm4(uint32_t* d, const void* p) {
    uint32_t a = (uint32_t)__cvta_generic_to_shared(p);
    asm volatile("ldmatrix.sync.aligned.m8n8.x4.shared.b16 {%0,%1,%2,%3}, [%4];"
                 : "=r"(d[0]), "=r"(d[1]), "=r"(d[2]), "=r"(d[3]) : "r"(a));
}
__device__ __forceinline__ void ldsm4t(uint32_t* d, const void* p) {
    uint32_t a = (uint32_t)__cvta_generic_to_shared(p);
    asm volatile("ldmatrix.sync.aligned.m8n8.x4.trans.shared.b16 {%0,%1,%2,%3}, [%4];"
                 : "=r"(d[0]), "=r"(d[1]), "=r"(d[2]), "=r"(d[3]) : "r"(a));
}
__device__ __forceinline__ void mma16816(float* c, const uint32_t* a,
                                         uint32_t b0, uint32_t b1) {
    asm volatile(
        "mma.sync.aligned.m16n8k16.row.col.f32.f16.f16.f32 "
        "{%0,%1,%2,%3}, {%4,%5,%6,%7}, {%8,%9}, {%0,%1,%2,%3};"
        : "+f"(c[0]), "+f"(c[1]), "+f"(c[2]), "+f"(c[3])
        : "r"(a[0]), "r"(a[1]), "r"(a[2]), "r"(a[3]), "r"(b0), "r"(b1));
}

// ---------------------------------------------------------------------------
// GEMM: C[rows,256] = A[rows,K] @ W[K,256] fp32 SIMT; epilogue emits fp16 hi/lo
// ---------------------------------------------------------------------------
__global__ __launch_bounds__(256) void gemm256(
    const float* __restrict__ A, const float* __restrict__ W,
    __half* __restrict__ Chi, __half* __restrict__ Clo, int K)
{
    __shared__ __align__(16) float As[16][128];
    __shared__ __align__(16) float Bs[16][64];

    const int t   = threadIdx.x;
    const int m0  = blockIdx.x * 128;
    const int nc0 = blockIdx.y * 64;
    const int tx  = t & 15;
    const int ty  = t >> 4;

    const int arow = t >> 1;
    const int akq  = (t & 1) * 8;
    const int brow = t >> 4;
    const int bcol = (t & 15) * 4;

    const float* Ap = A + (size_t)(m0 + arow) * K + akq;
    const float* Wp = W + (size_t)brow * 256 + nc0 + bcol;

    float acc[8][4];
#pragma unroll
    for (int i = 0; i < 8; ++i)
#pragma unroll
        for (int j = 0; j < 4; ++j) acc[i][j] = 0.f;

    for (int k0 = 0; k0 < K; k0 += 16) {
        float4 a0 = *(const float4*)(Ap + k0);
        float4 a1 = *(const float4*)(Ap + k0 + 4);
        float4 bv = *(const float4*)(Wp + (size_t)k0 * 256);
        __syncthreads();
        As[akq + 0][arow] = a0.x; As[akq + 1][arow] = a0.y;
        As[akq + 2][arow] = a0.z; As[akq + 3][arow] = a0.w;
        As[akq + 4][arow] = a1.x; As[akq + 5][arow] = a1.y;
        As[akq + 6][arow] = a1.z; As[akq + 7][arow] = a1.w;
        *(float4*)&Bs[brow][bcol] = bv;
        __syncthreads();
#pragma unroll
        for (int kk = 0; kk < 16; ++kk) {
            float4 av0 = *(const float4*)&As[kk][ty * 8];
            float4 av1 = *(const float4*)&As[kk][ty * 8 + 4];
            float4 b2  = *(const float4*)&Bs[kk][tx * 4];
            float ar[8] = {av0.x, av0.y, av0.z, av0.w, av1.x, av1.y, av1.z, av1.w};
#pragma unroll
            for (int i = 0; i < 8; ++i) {
                acc[i][0] += ar[i] * b2.x;
                acc[i][1] += ar[i] * b2.y;
                acc[i][2] += ar[i] * b2.z;
                acc[i][3] += ar[i] * b2.w;
            }
        }
    }
#pragma unroll
    for (int i = 0; i < 8; ++i) {
        size_t off = (size_t)(m0 + ty * 8 + i) * 256 + nc0 + tx * 4;
#pragma unroll
        for (int j = 0; j < 4; j += 2) {
            float x = acc[i][j], y = acc[i][j + 1];
            __half2 hi = __floats2half2_rn(x, y);
            float rx = x - __low2float(hi);
            float ry = y - __high2float(hi);
            __half2 lo = __floats2half2_rn(rx, ry);
            *(__half2*)&Chi[off + j] = hi;
            *(__half2*)&Clo[off + j] = lo;
        }
    }
}

// ---------------------------------------------------------------------------
// e_k = h . a_k for 3 vectors, h = hi + lo
// ---------------------------------------------------------------------------
__global__ __launch_bounds__(256) void edot3_kernel(
    const __half* __restrict__ hhi, const __half* __restrict__ hlo,
    const float* __restrict__ a0, const float* __restrict__ a1,
    const float* __restrict__ a2,
    float* __restrict__ e0, float* __restrict__ e1, float* __restrict__ e2)
{
    const int r = blockIdx.x * 8 + (threadIdx.x >> 5);
    const int lane = threadIdx.x & 31;
    const __half* ph = hhi + (size_t)r * 256;
    const __half* pl = hlo + (size_t)r * 256;
    float s0 = 0.f, s1 = 0.f, s2 = 0.f;
#pragma unroll
    for (int i = 0; i < 8; ++i) {
        int c = lane + i * 32;
        float x = __half2float(ph[c]) + __half2float(pl[c]);
        s0 += x * a0[c];
        s1 += x * a1[c];
        s2 += x * a2[c];
    }
#pragma unroll
    for (int o = 16; o > 0; o >>= 1) {
        s0 += __shfl_xor_sync(0xffffffffu, s0, o);
        s1 += __shfl_xor_sync(0xffffffffu, s1, o);
        s2 += __shfl_xor_sync(0xffffffffu, s2, o);
    }
    if (lane == 0) { e0[r] = s0; e1[r] = s1; e2[r] = s2; }
}

// Per-batch max of e2
__global__ __launch_bounds__(256) void bmax_kernel(
    const float* __restrict__ e2, float* __restrict__ mx, int M)
{
    __shared__ float red[256];
    const int b = blockIdx.x;
    const int t = threadIdx.x;
    const float* p = e2 + (size_t)b * M;
    float m = -3.4e38f;
    for (int i = t; i < M; i += 256) m = fmaxf(m, p[i]);
    red[t] = m;
    __syncthreads();
    for (int s = 128; s > 0; s >>= 1) {
        if (t < s) red[t] = fmaxf(red[t], red[t + s]);
        __syncthreads();
    }
    if (t == 0) mx[b] = red[0];
}

// P2 = exp(e2 - mx), Q2 = exp(0.2*(e2 - mx))
__global__ __launch_bounds__(256) void pq_kernel(
    const float* __restrict__ e2, const float* __restrict__ mx,
    float* __restrict__ P2, float* __restrict__ Q2, int M)
{
    const int b = blockIdx.y;
    const int i = blockIdx.x * 256 + threadIdx.x;
    float d = e2[(size_t)b * M + i] - mx[b];
    P2[(size_t)b * M + i] = __expf(d);
    Q2[(size_t)b * M + i] = __expf(0.2f * d);
}

// ---------------------------------------------------------------------------
// Fused masked attention on tensor cores (mma.sync m16n8k16)
// CTA: 64 rows x 256 cols, K-chunk 32 neighbors. g in fp16 hi+lo (2 passes).
// ---------------------------------------------------------------------------
__global__ __launch_bounds__(256, 2) void att_mma_kernel(
    const __half* __restrict__ ghi, const __half* __restrict__ glo,
    const int* __restrict__ adj,
    const float* __restrict__ e1, const float* __restrict__ mx,
    const float* __restrict__ P2, const float* __restrict__ Q2,
    const float* __restrict__ bias,
    float* __restrict__ out, int N, int M)
{
    __shared__ __align__(16) __half sW[64 * 40];      // w tile, stride 40 halves
    __shared__ __align__(16) __half sBhi[32 * 264];   // g hi, stride 264
    __shared__ __align__(16) __half sBlo[32 * 264];
    __shared__ float sP1[64], sQ1[64], sSum[64], sDeg[64];

    const int t    = threadIdx.x;
    const int lane = t & 31;
    const int wid  = t >> 5;
    const int b    = blockIdx.y;
    const int n0   = blockIdx.x * 64;

    if (t < 64) {
        float v = e1[(size_t)b * N + n0 + t] + mx[b];
        float sh = fmaxf(v, 0.2f * v);         // shift = lrelu(e1+mx)
        sP1[t] = __expf(v - sh);
        sQ1[t] = __expf(0.2f * v - sh);
        sSum[t] = 0.f;
        sDeg[t] = 0.f;
    }

    float c[16][4];
#pragma unroll
    for (int i = 0; i < 16; ++i)
#pragma unroll
        for (int j = 0; j < 4; ++j) c[i][j] = 0.f;

    // B-load mapping: row k = t>>3, cols (t&7)*32 .. +31 (4 uint4 per array)
    const int bk = t >> 3;
    const int bc = (t & 7) * 32;
    const uint4* ghp = (const uint4*)(ghi + ((size_t)b * M + bk) * 256 + bc);
    const uint4* glp = (const uint4*)(glo + ((size_t)b * M + bk) * 256 + bc);
    uint4* sbh = (uint4*)&sBhi[bk * 264 + bc];
    uint4* sbl = (uint4*)&sBlo[bk * 264 + bc];

    // w-gen mapping: row r = t>>2, cols (t&3)*8 .. +7
    const int wr = t >> 2;
    const int wc = (t & 3) * 8;
    const int* adjp = adj + ((size_t)b * N + n0 + wr) * M + wc;
    const float* p2p = P2 + (size_t)b * M + wc;
    const float* q2p = Q2 + (size_t)b * M + wc;

    // MMA mapping: warp -> rows (wid&3)*16, cols (wid>>2)*128
    const int r0  = (wid & 3) * 16;
    const int cbq = (wid >> 2) * 128;
    const __half* aAddr0 = &sW[(r0 + (lane & 15)) * 40 + (lane >> 4) * 8];
    const __half* aAddr1 = aAddr0 + 16;
    const int bRowOff = (lane & 15) * 264 + cbq + (lane >> 4) * 8;

    __syncthreads();
    const float P1r = sP1[wr];
    const float Q1r = sQ1[wr];

    for (int m0 = 0; m0 < M; m0 += 32) {
        // ---- load g chunk (hi+lo); one row = 256 halves = 32 uint4 ----
        const size_t gstep = (size_t)m0 * 32;
#pragma unroll
        for (int j = 0; j < 4; ++j) {
            sbh[j] = ghp[gstep + j];
            sbl[j] = glp[gstep + j];
        }

        // ---- w tile: fp32 compute, one fp16 rounding ----
        {
            unsigned short us[8];
            float ssum = 0.f;
            float cnt = 0.f;
#pragma unroll
            for (int j = 0; j < 2; ++j) {
                int4 a4 = *(const int4*)(adjp + m0 + j * 4);
                float4 p4 = *(const float4*)(p2p + m0 + j * 4);
                float4 q4 = *(const float4*)(q2p + m0 + j * 4);
                int av[4] = {a4.x, a4.y, a4.z, a4.w};
                float pv[4] = {p4.x, p4.y, p4.z, p4.w};
                float qv[4] = {q4.x, q4.y, q4.z, q4.w};
#pragma unroll
                for (int q = 0; q < 4; ++q) {
                    float w = fmaxf(P1r * pv[q], Q1r * qv[q]);
                    __half hw = __float2half_rn(w);
                    bool on = av[q] > 0;
                    unsigned short u = on ? __half_as_ushort(hw) : (unsigned short)0;
                    us[j * 4 + q] = u;
                    if (on) { ssum += __half2float(hw); cnt += 1.f; }
                }
            }
            uint4 v;
            v.x = (uint32_t)us[0] | ((uint32_t)us[1] << 16);
            v.y = (uint32_t)us[2] | ((uint32_t)us[3] << 16);
            v.z = (uint32_t)us[4] | ((uint32_t)us[5] << 16);
            v.w = (uint32_t)us[6] | ((uint32_t)us[7] << 16);
            *(uint4*)&sW[wr * 40 + wc] = v;
            ssum += __shfl_xor_sync(0xffffffffu, ssum, 1);
            ssum += __shfl_xor_sync(0xffffffffu, ssum, 2);
            cnt  += __shfl_xor_sync(0xffffffffu, cnt, 1);
            cnt  += __shfl_xor_sync(0xffffffffu, cnt, 2);
            if ((t & 3) == 0) { sSum[wr] += ssum; sDeg[wr] += cnt; }
        }
        __syncthreads();

        // ---- MMA over this chunk ----
        uint32_t afr[2][4];
        ldsm4(afr[0], aAddr0);
        ldsm4(afr[1], aAddr1);
#pragma unroll
        for (int kk = 0; kk < 2; ++kk) {
#pragma unroll
            for (int nb = 0; nb < 8; ++nb) {
                uint32_t bh[4], bl[4];
                ldsm4t(bh, &sBhi[kk * 16 * 264 + bRowOff + nb * 16]);
                mma16816(c[nb * 2],     afr[kk], bh[0], bh[1]);
                mma16816(c[nb * 2 + 1], afr[kk], bh[2], bh[3]);
                ldsm4t(bl, &sBlo[kk * 16 * 264 + bRowOff + nb * 16]);
                mma16816(c[nb * 2],     afr[kk], bl[0], bl[1]);
                mma16816(c[nb * 2 + 1], afr[kk], bl[2], bl[3]);
            }
        }
        __syncthreads();
    }

    // ---- epilogue ----
    const int rlo = r0 + (lane >> 2);
    const int rhi = rlo + 8;
    float slo = (sDeg[rlo] > 0.f && sSum[rlo] > 0.f) ? sDeg[rlo] / sSum[rlo] : 0.f;
    float shi = (sDeg[rhi] > 0.f && sSum[rhi] > 0.f) ? sDeg[rhi] / sSum[rhi] : 0.f;
    float* olo = out + ((size_t)b * N + n0 + rlo) * 256;
    float* ohi = out + ((size_t)b * N + n0 + rhi) * 256;
#pragma unroll
    for (int j = 0; j < 16; ++j) {
        int col = cbq + (j >> 1) * 16 + (j & 1) * 8 + (lane & 3) * 2;
        float b0 = bias[col], b1 = bias[col + 1];
        float2 v0 = make_float2(c[j][0] * slo + b0, c[j][1] * slo + b1);
        float2 v1 = make_float2(c[j][2] * shi + b0, c[j][3] * shi + b1);
        *(float2*)(olo + col) = v0;
        *(float2*)(ohi + col) = v1;
    }
}

// ---------------------------------------------------------------------------
// Launch
// ---------------------------------------------------------------------------
extern "C" void kernel_launch(void* const* d_in, const int* in_sizes, int n_in,
                              void* d_out, int out_size)
{
    const float* x0   = (const float*)d_in[0];
    const float* x1   = (const float*)d_in[1];
    const float* W0   = (const float*)d_in[2];
    const float* W1   = (const float*)d_in[3];
    const float* a1_0 = (const float*)d_in[4];
    const float* a2_0 = (const float*)d_in[5];
    const float* a1_1 = (const float*)d_in[6];
    const float* a2_1 = (const float*)d_in[7];
    const float* bias = (const float*)d_in[8];
    const int* adj00  = (const int*)d_in[9];
    const int* adj01  = (const int*)d_in[10];
    const int* adj10  = (const int*)d_in[11];
    const int* adj11  = (const int*)d_in[12];
    float* out = (float*)d_out;

    __half *h0hi, *h0lo, *h1hi, *h1lo;
    float *eA, *eB, *eC, *eD, *eE, *eF, *mx, *P2, *Q2;
    cudaGetSymbolAddress((void**)&h0hi, g_h0hi);
    cudaGetSymbolAddress((void**)&h0lo, g_h0lo);
    cudaGetSymbolAddress((void**)&h1hi, g_h1hi);
    cudaGetSymbolAddress((void**)&h1lo, g_h1lo);
    cudaGetSymbolAddress((void**)&eA, g_eA);
    cudaGetSymbolAddress((void**)&eB, g_eB);
    cudaGetSymbolAddress((void**)&eC, g_eC);
    cudaGetSymbolAddress((void**)&eD, g_eD);
    cudaGetSymbolAddress((void**)&eE, g_eE);
    cudaGetSymbolAddress((void**)&eF, g_eF);
    cudaGetSymbolAddress((void**)&mx, g_mx);
    cudaGetSymbolAddress((void**)&P2, g_P2);
    cudaGetSymbolAddress((void**)&Q2, g_Q2);

    const int R0 = BATCH * N1;
    const int R1 = BATCH * N2;

    // P2/Q2 segment offsets per attention block (col sides: eB,eC,eE,eF)
    const size_t o0 = 0;
    const size_t o1 = (size_t)BATCH * N1;
    const size_t o2 = o1 + (size_t)BATCH * N2;
    const size_t o3 = o2 + (size_t)BATCH * N1;

    gemm256<<<dim3(R0 / 128, 4), 256>>>(x0, W0, h0hi, h0lo, F0K);
    gemm256<<<dim3(R1 / 128, 4), 256>>>(x1, W1, h1hi, h1lo, F1K);

    edot3_kernel<<<R0 / 8, 256>>>(h0hi, h0lo, a1_0, a2_0, a2_1, eA, eB, eE);
    edot3_kernel<<<R1 / 8, 256>>>(h1hi, h1lo, a2_0, a1_1, a2_1, eC, eD, eF);

    bmax_kernel<<<BATCH, 256>>>(eB, mx + 0 * BATCH, N1);
    bmax_kernel<<<BATCH, 256>>>(eC, mx + 1 * BATCH, N2);
    bmax_kernel<<<BATCH, 256>>>(eE, mx + 2 * BATCH, N1);
    bmax_kernel<<<BATCH, 256>>>(eF, mx + 3 * BATCH, N2);

    pq_kernel<<<dim3(N1 / 256, BATCH), 256>>>(eB, mx + 0 * BATCH, P2 + o0, Q2 + o0, N1);
    pq_kernel<<<dim3(N2 / 256, BATCH), 256>>>(eC, mx + 1 * BATCH, P2 + o1, Q2 + o1, N2);
    pq_kernel<<<dim3(N1 / 256, BATCH), 256>>>(eE, mx + 2 * BATCH, P2 + o2, Q2 + o2, N1);
    pq_kernel<<<dim3(N2 / 256, BATCH), 256>>>(eF, mx + 3 * BATCH, P2 + o3, Q2 + o3, N2);

    float* o00 = out;
    float* o01 = out + (size_t)BATCH * N1 * 256;
    float* o10 = o01 + (size_t)BATCH * N1 * 256;
    float* o11 = o10 + (size_t)BATCH * N2 * 256;

    att_mma_kernel<<<dim3(N1 / 64, BATCH), 256>>>(
        h0hi, h0lo, adj00, eA, mx + 0 * BATCH, P2 + o0, Q2 + o0, bias, o00, N1, N1);
    att_mma_kernel<<<dim3(N1 / 64, BATCH), 256>>>(
        h1hi, h1lo, adj01, eA, mx + 1 * BATCH, P2 + o1, Q2 + o1, bias, o01, N1, N2);
    att_mma_kernel<<<dim3(N2 / 64, BATCH), 256>>>(
        h0hi, h0lo, adj10, eD, mx + 2 * BATCH, P2 + o2, Q2 + o2, bias, o10, N2, N1);
    att_mma_kernel<<<dim3(N2 / 64, BATCH), 256>>>(
        h1hi, h1lo, adj11, eD, mx + 3 * BATCH, P2 + o3, Q2 + o3, bias, o11, N2, N2);
}

// round 6
// speedup vs baseline: 1.9856x; 1.1696x over previous
#include <cuda_runtime.h>
#include <cuda_fp16.h>
#include <cstdint>
#include <cstddef>

#define BATCH 64
#define N1 1024
#define N2 512
#define F0K 512
#define F1K 384

// ---------------------------------------------------------------------------
// Scratch
// ---------------------------------------------------------------------------
__device__ __half g_h0hi[(size_t)BATCH * N1 * 256];
__device__ __half g_h0lo[(size_t)BATCH * N1 * 256];
__device__ __half g_h1hi[(size_t)BATCH * N2 * 256];
__device__ __half g_h1lo[(size_t)BATCH * N2 * 256];
__device__ float g_eA[BATCH * N1];
__device__ float g_eB[BATCH * N1];
__device__ float g_eC[BATCH * N2];
__device__ float g_eD[BATCH * N2];
__device__ float g_eE[BATCH * N1];
__device__ float g_eF[BATCH * N2];
__device__ float g_mx[4 * BATCH];
__device__ float g_P2[2 * BATCH * (N1 + N2)];
__device__ float g_Q2[2 * BATCH * (N1 + N2)];

// ---------------------------------------------------------------------------
// mma.sync / ldmatrix helpers (sm_80 PTX, valid at base sm_103 target)
// ---------------------------------------------------------------------------
__device__ __forceinline__ void ldsm4(uint32_t* d, const void* p) {
    uint32_t a = (uint32_t)__cvta_generic_to_shared(p);
    asm volatile("ldmatrix.sync.aligned.m8n8.x4.shared.b16 {%0,%1,%2,%3}, [%4];"
                 : "=r"(d[0]), "=r"(d[1]), "=r"(d[2]), "=r"(d[3]) : "r"(a));
}
__device__ __forceinline__ void ldsm4t(uint32_t* d, const void* p) {
    uint32_t a = (uint32_t)__cvta_generic_to_shared(p);
    asm volatile("ldmatrix.sync.aligned.m8n8.x4.trans.shared.b16 {%0,%1,%2,%3}, [%4];"
                 : "=r"(d[0]), "=r"(d[1]), "=r"(d[2]), "=r"(d[3]) : "r"(a));
}
__device__ __forceinline__ void mma16816(float* c, const uint32_t* a,
                                         uint32_t b0, uint32_t b1) {
    asm volatile(
        "mma.sync.aligned.m16n8k16.row.col.f32.f16.f16.f32 "
        "{%0,%1,%2,%3}, {%4,%5,%6,%7}, {%8,%9}, {%0,%1,%2,%3};"
        : "+f"(c[0]), "+f"(c[1]), "+f"(c[2]), "+f"(c[3])
        : "r"(a[0]), "r"(a[1]), "r"(a[2]), "r"(a[3]), "r"(b0), "r"(b1));
}

// ---------------------------------------------------------------------------
// Tensor-core GEMM: C[rows,256] = A[rows,K] @ W[K,256]
// fp16 hi/lo split of BOTH operands (on the fly), 3 MMA passes.
// BM=128, BN=128, BK=32, 256 threads (8 warps, 4m x 2n of 32x64 each).
// Epilogue emits fp16 hi/lo of the fp32 result.
// ---------------------------------------------------------------------------
__global__ __launch_bounds__(256) void gemm_mma(
    const float* __restrict__ A, const float* __restrict__ W,
    __half* __restrict__ Chi, __half* __restrict__ Clo, int K)
{
    __shared__ __align__(16) __half sAhi[128 * 40];   // [128][32+8]
    __shared__ __align__(16) __half sAlo[128 * 40];
    __shared__ __align__(16) __half sWhi[32 * 136];   // [32][128+8]
    __shared__ __align__(16) __half sWlo[32 * 136];

    const int t   = threadIdx.x;
    const int lane = t & 31;
    const int wid  = t >> 5;
    const int m0  = blockIdx.x * 128;
    const int nc0 = blockIdx.y * 128;

    // A staging: row = t>>1 (128 rows), cols (t&1)*16 .. +15
    const int ar = t >> 1;
    const int ac = (t & 1) * 16;
    const float* Ap = A + (size_t)(m0 + ar) * K + ac;
    // W staging: row k = t>>3 (32 rows), cols (t&7)*16 .. +15
    const int wk = t >> 3;
    const int wc = (t & 7) * 16;
    const float* Wp = W + (size_t)wk * 256 + nc0 + wc;

    // MMA mapping: warp -> rows (wid&3)*32, cols (wid>>2)*64
    const int am0 = (wid & 3) * 32;
    const int cn0 = (wid >> 2) * 64;

    float c[8][4];   // 2 m-tiles x 4 n16-groups... actually [mt*4 + nt2] layout below
    // c[mt][nt] with mt in {0,1} (16 rows each), nt in {0..7} (8 cols each):
    // index c[mt*4 + (nt>>1)][...] would be messy; use flat [16][4]:
    float cf[16][4];
#pragma unroll
    for (int i = 0; i < 16; ++i)
#pragma unroll
        for (int j = 0; j < 4; ++j) cf[i][j] = 0.f;
    (void)c;

    for (int k0 = 0; k0 < K; k0 += 32) {
        // ---- stage A (128x32 fp32 -> hi/lo fp16) ----
#pragma unroll
        for (int j = 0; j < 4; ++j) {
            float4 v = *(const float4*)(Ap + k0 + j * 4);
            __half2 h0 = __floats2half2_rn(v.x, v.y);
            __half2 h1 = __floats2half2_rn(v.z, v.w);
            __half2 l0 = __floats2half2_rn(v.x - __low2float(h0), v.y - __high2float(h0));
            __half2 l1 = __floats2half2_rn(v.z - __low2float(h1), v.w - __high2float(h1));
            int off = ar * 40 + ac + j * 4;
            *(__half2*)&sAhi[off]     = h0;
            *(__half2*)&sAhi[off + 2] = h1;
            *(__half2*)&sAlo[off]     = l0;
            *(__half2*)&sAlo[off + 2] = l1;
        }
        // ---- stage W (32x128 fp32 -> hi/lo fp16) ----
#pragma unroll
        for (int j = 0; j < 4; ++j) {
            float4 v = *(const float4*)(Wp + (size_t)k0 * 256 + j * 4);
            __half2 h0 = __floats2half2_rn(v.x, v.y);
            __half2 h1 = __floats2half2_rn(v.z, v.w);
            __half2 l0 = __floats2half2_rn(v.x - __low2float(h0), v.y - __high2float(h0));
            __half2 l1 = __floats2half2_rn(v.z - __low2float(h1), v.w - __high2float(h1));
            int off = wk * 136 + wc + j * 4;
            *(__half2*)&sWhi[off]     = h0;
            *(__half2*)&sWhi[off + 2] = h1;
            *(__half2*)&sWlo[off]     = l0;
            *(__half2*)&sWlo[off + 2] = l1;
        }
        __syncthreads();

        // ---- MMA: 2 k-steps, 2 m-tiles, 4 n16-groups, 3 passes ----
#pragma unroll
        for (int kk = 0; kk < 2; ++kk) {
#pragma unroll
            for (int mt = 0; mt < 2; ++mt) {
                uint32_t ah[4], al[4];
                const int arow = am0 + mt * 16 + (lane & 15);
                const int acol = kk * 16 + (lane >> 4) * 8;
                ldsm4(ah, &sAhi[arow * 40 + acol]);
                ldsm4(al, &sAlo[arow * 40 + acol]);
#pragma unroll
                for (int nt = 0; nt < 4; ++nt) {
                    uint32_t bh[4], bl[4];
                    const int boff = (kk * 16 + (lane & 15)) * 136 + cn0 +
                                     nt * 16 + (lane >> 4) * 8;
                    ldsm4t(bh, &sWhi[boff]);
                    ldsm4t(bl, &sWlo[boff]);
                    float* c0 = cf[mt * 8 + nt * 2];
                    float* c1 = cf[mt * 8 + nt * 2 + 1];
                    mma16816(c0, ah, bh[0], bh[1]);
                    mma16816(c1, ah, bh[2], bh[3]);
                    mma16816(c0, ah, bl[0], bl[1]);
                    mma16816(c1, ah, bl[2], bl[3]);
                    mma16816(c0, al, bh[0], bh[1]);
                    mma16816(c1, al, bh[2], bh[3]);
                }
            }
        }
        __syncthreads();
    }

    // ---- epilogue: fp32 acc -> fp16 hi/lo ----
    const int rlo = am0 + (lane >> 2);
#pragma unroll
    for (int mt = 0; mt < 2; ++mt) {
#pragma unroll
        for (int j = 0; j < 8; ++j) {
            int nt = j >> 1;
            int half8 = j & 1;
            float* cc = cf[mt * 8 + j];
            int row = rlo + mt * 16 + half8 * 8;
            // wait: half8 indexes the second n8 of the n16 group, not rows.
            row = rlo + mt * 16;
            int col = nc0 + cn0 + nt * 16 + half8 * 8 + (lane & 3) * 2;
            // c fragment: c[0],c[1] -> row (lane>>2); c[2],c[3] -> row +8
            {
                float x = cc[0], y = cc[1];
                __half2 hi = __floats2half2_rn(x, y);
                __half2 lo = __floats2half2_rn(x - __low2float(hi), y - __high2float(hi));
                size_t off = (size_t)(m0 + row) * 256 + col;
                *(__half2*)&Chi[off] = hi;
                *(__half2*)&Clo[off] = lo;
            }
            {
                float x = cc[2], y = cc[3];
                __half2 hi = __floats2half2_rn(x, y);
                __half2 lo = __floats2half2_rn(x - __low2float(hi), y - __high2float(hi));
                size_t off = (size_t)(m0 + row + 8) * 256 + col;
                *(__half2*)&Chi[off] = hi;
                *(__half2*)&Clo[off] = lo;
            }
        }
    }
}

// ---------------------------------------------------------------------------
// e_k = h . a_k for 3 vectors, h = hi + lo
// ---------------------------------------------------------------------------
__global__ __launch_bounds__(256) void edot3_kernel(
    const __half* __restrict__ hhi, const __half* __restrict__ hlo,
    const float* __restrict__ a0, const float* __restrict__ a1,
    const float* __restrict__ a2,
    float* __restrict__ e0, float* __restrict__ e1, float* __restrict__ e2)
{
    const int r = blockIdx.x * 8 + (threadIdx.x >> 5);
    const int lane = threadIdx.x & 31;
    const __half* ph = hhi + (size_t)r * 256;
    const __half* pl = hlo + (size_t)r * 256;
    float s0 = 0.f, s1 = 0.f, s2 = 0.f;
#pragma unroll
    for (int i = 0; i < 8; ++i) {
        int c = lane + i * 32;
        float x = __half2float(ph[c]) + __half2float(pl[c]);
        s0 += x * a0[c];
        s1 += x * a1[c];
        s2 += x * a2[c];
    }
#pragma unroll
    for (int o = 16; o > 0; o >>= 1) {
        s0 += __shfl_xor_sync(0xffffffffu, s0, o);
        s1 += __shfl_xor_sync(0xffffffffu, s1, o);
        s2 += __shfl_xor_sync(0xffffffffu, s2, o);
    }
    if (lane == 0) { e0[r] = s0; e1[r] = s1; e2[r] = s2; }
}

// Per-batch max of e2
__global__ __launch_bounds__(256) void bmax_kernel(
    const float* __restrict__ e2, float* __restrict__ mx, int M)
{
    __shared__ float red[256];
    const int b = blockIdx.x;
    const int t = threadIdx.x;
    const float* p = e2 + (size_t)b * M;
    float m = -3.4e38f;
    for (int i = t; i < M; i += 256) m = fmaxf(m, p[i]);
    red[t] = m;
    __syncthreads();
    for (int s = 128; s > 0; s >>= 1) {
        if (t < s) red[t] = fmaxf(red[t], red[t + s]);
        __syncthreads();
    }
    if (t == 0) mx[b] = red[0];
}

// P2 = exp(e2 - mx), Q2 = exp(0.2*(e2 - mx))
__global__ __launch_bounds__(256) void pq_kernel(
    const float* __restrict__ e2, const float* __restrict__ mx,
    float* __restrict__ P2, float* __restrict__ Q2, int M)
{
    const int b = blockIdx.y;
    const int i = blockIdx.x * 256 + threadIdx.x;
    float d = e2[(size_t)b * M + i] - mx[b];
    P2[(size_t)b * M + i] = __expf(d);
    Q2[(size_t)b * M + i] = __expf(0.2f * d);
}

// ---------------------------------------------------------------------------
// Fused masked attention on tensor cores (mma.sync m16n8k16)
// CTA: 64 rows x 256 cols, K-chunk 32 neighbors. g in fp16 hi+lo (2 passes).
// ---------------------------------------------------------------------------
__global__ __launch_bounds__(256, 2) void att_mma_kernel(
    const __half* __restrict__ ghi, const __half* __restrict__ glo,
    const int* __restrict__ adj,
    const float* __restrict__ e1, const float* __restrict__ mx,
    const float* __restrict__ P2, const float* __restrict__ Q2,
    const float* __restrict__ bias,
    float* __restrict__ out, int N, int M)
{
    __shared__ __align__(16) __half sW[64 * 40];      // w tile, stride 40 halves
    __shared__ __align__(16) __half sBhi[32 * 264];   // g hi, stride 264
    __shared__ __align__(16) __half sBlo[32 * 264];
    __shared__ float sP1[64], sQ1[64], sSum[64], sDeg[64];

    const int t    = threadIdx.x;
    const int lane = t & 31;
    const int wid  = t >> 5;
    const int b    = blockIdx.y;
    const int n0   = blockIdx.x * 64;

    if (t < 64) {
        float v = e1[(size_t)b * N + n0 + t] + mx[b];
        float sh = fmaxf(v, 0.2f * v);         // shift = lrelu(e1+mx)
        sP1[t] = __expf(v - sh);
        sQ1[t] = __expf(0.2f * v - sh);
        sSum[t] = 0.f;
        sDeg[t] = 0.f;
    }

    float c[16][4];
#pragma unroll
    for (int i = 0; i < 16; ++i)
#pragma unroll
        for (int j = 0; j < 4; ++j) c[i][j] = 0.f;

    // B-load mapping: row k = t>>3, cols (t&7)*32 .. +31 (4 uint4 per array)
    const int bk = t >> 3;
    const int bc = (t & 7) * 32;
    const uint4* ghp = (const uint4*)(ghi + ((size_t)b * M + bk) * 256 + bc);
    const uint4* glp = (const uint4*)(glo + ((size_t)b * M + bk) * 256 + bc);
    uint4* sbh = (uint4*)&sBhi[bk * 264 + bc];
    uint4* sbl = (uint4*)&sBlo[bk * 264 + bc];

    // w-gen mapping: row r = t>>2, cols (t&3)*8 .. +7
    const int wr = t >> 2;
    const int wc = (t & 3) * 8;
    const int* adjp = adj + ((size_t)b * N + n0 + wr) * M + wc;
    const float* p2p = P2 + (size_t)b * M + wc;
    const float* q2p = Q2 + (size_t)b * M + wc;

    // MMA mapping: warp -> rows (wid&3)*16, cols (wid>>2)*128
    const int r0  = (wid & 3) * 16;
    const int cbq = (wid >> 2) * 128;
    const __half* aAddr0 = &sW[(r0 + (lane & 15)) * 40 + (lane >> 4) * 8];
    const __half* aAddr1 = aAddr0 + 16;
    const int bRowOff = (lane & 15) * 264 + cbq + (lane >> 4) * 8;

    __syncthreads();
    const float P1r = sP1[wr];
    const float Q1r = sQ1[wr];

    for (int m0 = 0; m0 < M; m0 += 32) {
        // ---- load g chunk (hi+lo); one row = 256 halves = 32 uint4 ----
        const size_t gstep = (size_t)m0 * 32;
#pragma unroll
        for (int j = 0; j < 4; ++j) {
            sbh[j] = ghp[gstep + j];
            sbl[j] = glp[gstep + j];
        }

        // ---- w tile: fp32 compute, one fp16 rounding ----
        {
            unsigned short us[8];
            float ssum = 0.f;
            float cnt = 0.f;
#pragma unroll
            for (int j = 0; j < 2; ++j) {
                int4 a4 = *(const int4*)(adjp + m0 + j * 4);
                float4 p4 = *(const float4*)(p2p + m0 + j * 4);
                float4 q4 = *(const float4*)(q2p + m0 + j * 4);
                int av[4] = {a4.x, a4.y, a4.z, a4.w};
                float pv[4] = {p4.x, p4.y, p4.z, p4.w};
                float qv[4] = {q4.x, q4.y, q4.z, q4.w};
#pragma unroll
                for (int q = 0; q < 4; ++q) {
                    float w = fmaxf(P1r * pv[q], Q1r * qv[q]);
                    __half hw = __float2half_rn(w);
                    bool on = av[q] > 0;
                    unsigned short u = on ? __half_as_ushort(hw) : (unsigned short)0;
                    us[j * 4 + q] = u;
                    if (on) { ssum += __half2float(hw); cnt += 1.f; }
                }
            }
            uint4 v;
            v.x = (uint32_t)us[0] | ((uint32_t)us[1] << 16);
            v.y = (uint32_t)us[2] | ((uint32_t)us[3] << 16);
            v.z = (uint32_t)us[4] | ((uint32_t)us[5] << 16);
            v.w = (uint32_t)us[6] | ((uint32_t)us[7] << 16);
            *(uint4*)&sW[wr * 40 + wc] = v;
            ssum += __shfl_xor_sync(0xffffffffu, ssum, 1);
            ssum += __shfl_xor_sync(0xffffffffu, ssum, 2);
            cnt  += __shfl_xor_sync(0xffffffffu, cnt, 1);
            cnt  += __shfl_xor_sync(0xffffffffu, cnt, 2);
            if ((t & 3) == 0) { sSum[wr] += ssum; sDeg[wr] += cnt; }
        }
        __syncthreads();

        // ---- MMA over this chunk ----
        uint32_t afr[2][4];
        ldsm4(afr[0], aAddr0);
        ldsm4(afr[1], aAddr1);
#pragma unroll
        for (int kk = 0; kk < 2; ++kk) {
#pragma unroll
            for (int nb = 0; nb < 8; ++nb) {
                uint32_t bh[4], bl[4];
                ldsm4t(bh, &sBhi[kk * 16 * 264 + bRowOff + nb * 16]);
                mma16816(c[nb * 2],     afr[kk], bh[0], bh[1]);
                mma16816(c[nb * 2 + 1], afr[kk], bh[2], bh[3]);
                ldsm4t(bl, &sBlo[kk * 16 * 264 + bRowOff + nb * 16]);
                mma16816(c[nb * 2],     afr[kk], bl[0], bl[1]);
                mma16816(c[nb * 2 + 1], afr[kk], bl[2], bl[3]);
            }
        }
        __syncthreads();
    }

    // ---- epilogue ----
    const int rlo = r0 + (lane >> 2);
    const int rhi = rlo + 8;
    float slo = (sDeg[rlo] > 0.f && sSum[rlo] > 0.f) ? sDeg[rlo] / sSum[rlo] : 0.f;
    float shi = (sDeg[rhi] > 0.f && sSum[rhi] > 0.f) ? sDeg[rhi] / sSum[rhi] : 0.f;
    float* olo = out + ((size_t)b * N + n0 + rlo) * 256;
    float* ohi = out + ((size_t)b * N + n0 + rhi) * 256;
#pragma unroll
    for (int j = 0; j < 16; ++j) {
        int col = cbq + (j >> 1) * 16 + (j & 1) * 8 + (lane & 3) * 2;
        float b0 = bias[col], b1 = bias[col + 1];
        float2 v0 = make_float2(c[j][0] * slo + b0, c[j][1] * slo + b1);
        float2 v1 = make_float2(c[j][2] * shi + b0, c[j][3] * shi + b1);
        *(float2*)(olo + col) = v0;
        *(float2*)(ohi + col) = v1;
    }
}

// ---------------------------------------------------------------------------
// Launch
// ---------------------------------------------------------------------------
extern "C" void kernel_launch(void* const* d_in, const int* in_sizes, int n_in,
                              void* d_out, int out_size)
{
    const float* x0   = (const float*)d_in[0];
    const float* x1   = (const float*)d_in[1];
    const float* W0   = (const float*)d_in[2];
    const float* W1   = (const float*)d_in[3];
    const float* a1_0 = (const float*)d_in[4];
    const float* a2_0 = (const float*)d_in[5];
    const float* a1_1 = (const float*)d_in[6];
    const float* a2_1 = (const float*)d_in[7];
    const float* bias = (const float*)d_in[8];
    const int* adj00  = (const int*)d_in[9];
    const int* adj01  = (const int*)d_in[10];
    const int* adj10  = (const int*)d_in[11];
    const int* adj11  = (const int*)d_in[12];
    float* out = (float*)d_out;

    __half *h0hi, *h0lo, *h1hi, *h1lo;
    float *eA, *eB, *eC, *eD, *eE, *eF, *mx, *P2, *Q2;
    cudaGetSymbolAddress((void**)&h0hi, g_h0hi);
    cudaGetSymbolAddress((void**)&h0lo, g_h0lo);
    cudaGetSymbolAddress((void**)&h1hi, g_h1hi);
    cudaGetSymbolAddress((void**)&h1lo, g_h1lo);
    cudaGetSymbolAddress((void**)&eA, g_eA);
    cudaGetSymbolAddress((void**)&eB, g_eB);
    cudaGetSymbolAddress((void**)&eC, g_eC);
    cudaGetSymbolAddress((void**)&eD, g_eD);
    cudaGetSymbolAddress((void**)&eE, g_eE);
    cudaGetSymbolAddress((void**)&eF, g_eF);
    cudaGetSymbolAddress((void**)&mx, g_mx);
    cudaGetSymbolAddress((void**)&P2, g_P2);
    cudaGetSymbolAddress((void**)&Q2, g_Q2);

    const int R0 = BATCH * N1;
    const int R1 = BATCH * N2;

    // P2/Q2 segment offsets per attention block (col sides: eB,eC,eE,eF)
    const size_t o0 = 0;
    const size_t o1 = (size_t)BATCH * N1;
    const size_t o2 = o1 + (size_t)BATCH * N2;
    const size_t o3 = o2 + (size_t)BATCH * N1;

    gemm_mma<<<dim3(R0 / 128, 2), 256>>>(x0, W0, h0hi, h0lo, F0K);
    gemm_mma<<<dim3(R1 / 128, 2), 256>>>(x1, W1, h1hi, h1lo, F1K);

    edot3_kernel<<<R0 / 8, 256>>>(h0hi, h0lo, a1_0, a2_0, a2_1, eA, eB, eE);
    edot3_kernel<<<R1 / 8, 256>>>(h1hi, h1lo, a2_0, a1_1, a2_1, eC, eD, eF);

    bmax_kernel<<<BATCH, 256>>>(eB, mx + 0 * BATCH, N1);
    bmax_kernel<<<BATCH, 256>>>(eC, mx + 1 * BATCH, N2);
    bmax_kernel<<<BATCH, 256>>>(eE, mx + 2 * BATCH, N1);
    bmax_kernel<<<BATCH, 256>>>(eF, mx + 3 * BATCH, N2);

    pq_kernel<<<dim3(N1 / 256, BATCH), 256>>>(eB, mx + 0 * BATCH, P2 + o0, Q2 + o0, N1);
    pq_kernel<<<dim3(N2 / 256, BATCH), 256>>>(eC, mx + 1 * BATCH, P2 + o1, Q2 + o1, N2);
    pq_kernel<<<dim3(N1 / 256, BATCH), 256>>>(eE, mx + 2 * BATCH, P2 + o2, Q2 + o2, N1);
    pq_kernel<<<dim3(N2 / 256, BATCH), 256>>>(eF, mx + 3 * BATCH, P2 + o3, Q2 + o3, N2);

    float* o00 = out;
    float* o01 = out + (size_t)BATCH * N1 * 256;
    float* o10 = o01 + (size_t)BATCH * N1 * 256;
    float* o11 = o10 + (size_t)BATCH * N2 * 256;

    att_mma_kernel<<<dim3(N1 / 64, BATCH), 256>>>(
        h0hi, h0lo, adj00, eA, mx + 0 * BATCH, P2 + o0, Q2 + o0, bias, o00, N1, N1);
    att_mma_kernel<<<dim3(N1 / 64, BATCH), 256>>>(
        h1hi, h1lo, adj01, eA, mx + 1 * BATCH, P2 + o1, Q2 + o1, bias, o01, N1, N2);
    att_mma_kernel<<<dim3(N2 / 64, BATCH), 256>>>(
        h0hi, h0lo, adj10, eD, mx + 2 * BATCH, P2 + o2, Q2 + o2, bias, o10, N2, N1);
    att_mma_kernel<<<dim3(N2 / 64, BATCH), 256>>>(
        h1hi, h1lo, adj11, eD, mx + 3 * BATCH, P2 + o3, Q2 + o3, bias, o11, N2, N2);
}

// round 7
// speedup vs baseline: 2.6862x; 1.3528x over previous
#include <cuda_runtime.h>
#include <cuda_fp16.h>
#include <cstdint>
#include <cstddef>

#define BATCH 64
#define N1 1024
#define N2 512
#define F0K 512
#define F1K 384

// ---------------------------------------------------------------------------
// Scratch
// ---------------------------------------------------------------------------
__device__ __half g_h0hi[(size_t)BATCH * N1 * 256];
__device__ __half g_h0lo[(size_t)BATCH * N1 * 256];
__device__ __half g_h1hi[(size_t)BATCH * N2 * 256];
__device__ __half g_h1lo[(size_t)BATCH * N2 * 256];
__device__ float g_eA[BATCH * N1];
__device__ float g_eB[BATCH * N1];
__device__ float g_eC[BATCH * N2];
__device__ float g_eD[BATCH * N2];
__device__ float g_eE[BATCH * N1];
__device__ float g_eF[BATCH * N2];
__device__ float g_mx[4 * BATCH];
__device__ float g_P2[2 * BATCH * (N1 + N2)];
__device__ float g_Q2[2 * BATCH * (N1 + N2)];

// ---------------------------------------------------------------------------
// mma.sync / ldmatrix helpers (sm_80 PTX, valid at base sm_103 target)
// ---------------------------------------------------------------------------
__device__ __forceinline__ void ldsm4(uint32_t* d, const void* p) {
    uint32_t a = (uint32_t)__cvta_generic_to_shared(p);
    asm volatile("ldmatrix.sync.aligned.m8n8.x4.shared.b16 {%0,%1,%2,%3}, [%4];"
                 : "=r"(d[0]), "=r"(d[1]), "=r"(d[2]), "=r"(d[3]) : "r"(a));
}
__device__ __forceinline__ void ldsm4t(uint32_t* d, const void* p) {
    uint32_t a = (uint32_t)__cvta_generic_to_shared(p);
    asm volatile("ldmatrix.sync.aligned.m8n8.x4.trans.shared.b16 {%0,%1,%2,%3}, [%4];"
                 : "=r"(d[0]), "=r"(d[1]), "=r"(d[2]), "=r"(d[3]) : "r"(a));
}
__device__ __forceinline__ void mma16816(float* c, const uint32_t* a,
                                         uint32_t b0, uint32_t b1) {
    asm volatile(
        "mma.sync.aligned.m16n8k16.row.col.f32.f16.f16.f32 "
        "{%0,%1,%2,%3}, {%4,%5,%6,%7}, {%8,%9}, {%0,%1,%2,%3};"
        : "+f"(c[0]), "+f"(c[1]), "+f"(c[2]), "+f"(c[3])
        : "r"(a[0]), "r"(a[1]), "r"(a[2]), "r"(a[3]), "r"(b0), "r"(b1));
}

// ---------------------------------------------------------------------------
// Tensor-core GEMM: C[rows,256] = A[rows,K] @ W[K,256]
// fp16 hi/lo split of BOTH operands (on the fly), 3 MMA passes.
// BM=128, BN=128, BK=32, 256 threads (8 warps, 4m x 2n of 32x64 each).
// Epilogue emits fp16 hi/lo of the fp32 result.
// ---------------------------------------------------------------------------
__global__ __launch_bounds__(256) void gemm_mma(
    const float* __restrict__ A, const float* __restrict__ W,
    __half* __restrict__ Chi, __half* __restrict__ Clo, int K)
{
    __shared__ __align__(16) __half sAhi[128 * 40];   // [128][32+8]
    __shared__ __align__(16) __half sAlo[128 * 40];
    __shared__ __align__(16) __half sWhi[32 * 136];   // [32][128+8]
    __shared__ __align__(16) __half sWlo[32 * 136];

    const int t   = threadIdx.x;
    const int lane = t & 31;
    const int wid  = t >> 5;
    const int m0  = blockIdx.x * 128;
    const int nc0 = blockIdx.y * 128;

    // A staging: row = t>>1 (128 rows), cols (t&1)*16 .. +15
    const int ar = t >> 1;
    const int ac = (t & 1) * 16;
    const float* Ap = A + (size_t)(m0 + ar) * K + ac;
    // W staging: row k = t>>3 (32 rows), cols (t&7)*16 .. +15
    const int wk = t >> 3;
    const int wc = (t & 7) * 16;
    const float* Wp = W + (size_t)wk * 256 + nc0 + wc;

    // MMA mapping: warp -> rows (wid&3)*32, cols (wid>>2)*64
    const int am0 = (wid & 3) * 32;
    const int cn0 = (wid >> 2) * 64;

    float cf[16][4];
#pragma unroll
    for (int i = 0; i < 16; ++i)
#pragma unroll
        for (int j = 0; j < 4; ++j) cf[i][j] = 0.f;

    for (int k0 = 0; k0 < K; k0 += 32) {
        // ---- stage A (128x32 fp32 -> hi/lo fp16) ----
#pragma unroll
        for (int j = 0; j < 4; ++j) {
            float4 v = *(const float4*)(Ap + k0 + j * 4);
            __half2 h0 = __floats2half2_rn(v.x, v.y);
            __half2 h1 = __floats2half2_rn(v.z, v.w);
            __half2 l0 = __floats2half2_rn(v.x - __low2float(h0), v.y - __high2float(h0));
            __half2 l1 = __floats2half2_rn(v.z - __low2float(h1), v.w - __high2float(h1));
            int off = ar * 40 + ac + j * 4;
            *(__half2*)&sAhi[off]     = h0;
            *(__half2*)&sAhi[off + 2] = h1;
            *(__half2*)&sAlo[off]     = l0;
            *(__half2*)&sAlo[off + 2] = l1;
        }
        // ---- stage W (32x128 fp32 -> hi/lo fp16) ----
#pragma unroll
        for (int j = 0; j < 4; ++j) {
            float4 v = *(const float4*)(Wp + (size_t)k0 * 256 + j * 4);
            __half2 h0 = __floats2half2_rn(v.x, v.y);
            __half2 h1 = __floats2half2_rn(v.z, v.w);
            __half2 l0 = __floats2half2_rn(v.x - __low2float(h0), v.y - __high2float(h0));
            __half2 l1 = __floats2half2_rn(v.z - __low2float(h1), v.w - __high2float(h1));
            int off = wk * 136 + wc + j * 4;
            *(__half2*)&sWhi[off]     = h0;
            *(__half2*)&sWhi[off + 2] = h1;
            *(__half2*)&sWlo[off]     = l0;
            *(__half2*)&sWlo[off + 2] = l1;
        }
        __syncthreads();

        // ---- MMA: 2 k-steps, 2 m-tiles, 4 n16-groups, 3 passes ----
#pragma unroll
        for (int kk = 0; kk < 2; ++kk) {
#pragma unroll
            for (int mt = 0; mt < 2; ++mt) {
                uint32_t ah[4], al[4];
                const int arow = am0 + mt * 16 + (lane & 15);
                const int acol = kk * 16 + (lane >> 4) * 8;
                ldsm4(ah, &sAhi[arow * 40 + acol]);
                ldsm4(al, &sAlo[arow * 40 + acol]);
#pragma unroll
                for (int nt = 0; nt < 4; ++nt) {
                    uint32_t bh[4], bl[4];
                    const int boff = (kk * 16 + (lane & 15)) * 136 + cn0 +
                                     nt * 16 + (lane >> 4) * 8;
                    ldsm4t(bh, &sWhi[boff]);
                    ldsm4t(bl, &sWlo[boff]);
                    float* c0 = cf[mt * 8 + nt * 2];
                    float* c1 = cf[mt * 8 + nt * 2 + 1];
                    mma16816(c0, ah, bh[0], bh[1]);
                    mma16816(c1, ah, bh[2], bh[3]);
                    mma16816(c0, ah, bl[0], bl[1]);
                    mma16816(c1, ah, bl[2], bl[3]);
                    mma16816(c0, al, bh[0], bh[1]);
                    mma16816(c1, al, bh[2], bh[3]);
                }
            }
        }
        __syncthreads();
    }

    // ---- epilogue: fp32 acc -> fp16 hi/lo ----
    const int rlo = am0 + (lane >> 2);
#pragma unroll
    for (int mt = 0; mt < 2; ++mt) {
#pragma unroll
        for (int j = 0; j < 8; ++j) {
            int nt = j >> 1;
            int half8 = j & 1;
            float* cc = cf[mt * 8 + j];
            int row = rlo + mt * 16;
            int col = nc0 + cn0 + nt * 16 + half8 * 8 + (lane & 3) * 2;
            {
                float x = cc[0], y = cc[1];
                __half2 hi = __floats2half2_rn(x, y);
                __half2 lo = __floats2half2_rn(x - __low2float(hi), y - __high2float(hi));
                size_t off = (size_t)(m0 + row) * 256 + col;
                *(__half2*)&Chi[off] = hi;
                *(__half2*)&Clo[off] = lo;
            }
            {
                float x = cc[2], y = cc[3];
                __half2 hi = __floats2half2_rn(x, y);
                __half2 lo = __floats2half2_rn(x - __low2float(hi), y - __high2float(hi));
                size_t off = (size_t)(m0 + row + 8) * 256 + col;
                *(__half2*)&Chi[off] = hi;
                *(__half2*)&Clo[off] = lo;
            }
        }
    }
}

// ---------------------------------------------------------------------------
// e_k = h . a_k for 3 vectors, h = hi + lo
// ---------------------------------------------------------------------------
__global__ __launch_bounds__(256) void edot3_kernel(
    const __half* __restrict__ hhi, const __half* __restrict__ hlo,
    const float* __restrict__ a0, const float* __restrict__ a1,
    const float* __restrict__ a2,
    float* __restrict__ e0, float* __restrict__ e1, float* __restrict__ e2)
{
    const int r = blockIdx.x * 8 + (threadIdx.x >> 5);
    const int lane = threadIdx.x & 31;
    const __half* ph = hhi + (size_t)r * 256;
    const __half* pl = hlo + (size_t)r * 256;
    float s0 = 0.f, s1 = 0.f, s2 = 0.f;
#pragma unroll
    for (int i = 0; i < 8; ++i) {
        int c = lane + i * 32;
        float x = __half2float(ph[c]) + __half2float(pl[c]);
        s0 += x * a0[c];
        s1 += x * a1[c];
        s2 += x * a2[c];
    }
#pragma unroll
    for (int o = 16; o > 0; o >>= 1) {
        s0 += __shfl_xor_sync(0xffffffffu, s0, o);
        s1 += __shfl_xor_sync(0xffffffffu, s1, o);
        s2 += __shfl_xor_sync(0xffffffffu, s2, o);
    }
    if (lane == 0) { e0[r] = s0; e1[r] = s1; e2[r] = s2; }
}

// Per-batch max of e2
__global__ __launch_bounds__(256) void bmax_kernel(
    const float* __restrict__ e2, float* __restrict__ mx, int M)
{
    __shared__ float red[256];
    const int b = blockIdx.x;
    const int t = threadIdx.x;
    const float* p = e2 + (size_t)b * M;
    float m = -3.4e38f;
    for (int i = t; i < M; i += 256) m = fmaxf(m, p[i]);
    red[t] = m;
    __syncthreads();
    for (int s = 128; s > 0; s >>= 1) {
        if (t < s) red[t] = fmaxf(red[t], red[t + s]);
        __syncthreads();
    }
    if (t == 0) mx[b] = red[0];
}

// P2 = exp(e2 - mx), Q2 = exp(0.2*(e2 - mx))
__global__ __launch_bounds__(256) void pq_kernel(
    const float* __restrict__ e2, const float* __restrict__ mx,
    float* __restrict__ P2, float* __restrict__ Q2, int M)
{
    const int b = blockIdx.y;
    const int i = blockIdx.x * 256 + threadIdx.x;
    float d = e2[(size_t)b * M + i] - mx[b];
    P2[(size_t)b * M + i] = __expf(d);
    Q2[(size_t)b * M + i] = __expf(0.2f * d);
}

// ---------------------------------------------------------------------------
// Fused masked attention on tensor cores (mma.sync m16n8k16)
// CTA: 64 rows x 256 cols, K-chunk 32 neighbors. g in plain fp16 (hi only).
// ---------------------------------------------------------------------------
__global__ __launch_bounds__(256, 2) void att_mma_kernel(
    const __half* __restrict__ ghi,
    const int* __restrict__ adj,
    const float* __restrict__ e1, const float* __restrict__ mx,
    const float* __restrict__ P2, const float* __restrict__ Q2,
    const float* __restrict__ bias,
    float* __restrict__ out, int N, int M)
{
    __shared__ __align__(16) __half sW[64 * 40];      // w tile, stride 40 halves
    __shared__ __align__(16) __half sBhi[32 * 264];   // g hi, stride 264
    __shared__ float sP1[64], sQ1[64], sSum[64], sDeg[64];

    const int t    = threadIdx.x;
    const int lane = t & 31;
    const int wid  = t >> 5;
    const int b    = blockIdx.y;
    const int n0   = blockIdx.x * 64;

    if (t < 64) {
        float v = e1[(size_t)b * N + n0 + t] + mx[b];
        float sh = fmaxf(v, 0.2f * v);         // shift = lrelu(e1+mx)
        sP1[t] = __expf(v - sh);
        sQ1[t] = __expf(0.2f * v - sh);
        sSum[t] = 0.f;
        sDeg[t] = 0.f;
    }

    float c[16][4];
#pragma unroll
    for (int i = 0; i < 16; ++i)
#pragma unroll
        for (int j = 0; j < 4; ++j) c[i][j] = 0.f;

    // B-load mapping: row k = t>>3, cols (t&7)*32 .. +31 (4 uint4)
    const int bk = t >> 3;
    const int bc = (t & 7) * 32;
    const uint4* ghp = (const uint4*)(ghi + ((size_t)b * M + bk) * 256 + bc);
    uint4* sbh = (uint4*)&sBhi[bk * 264 + bc];

    // w-gen mapping: row r = t>>2, cols (t&3)*8 .. +7
    const int wr = t >> 2;
    const int wc = (t & 3) * 8;
    const int* adjp = adj + ((size_t)b * N + n0 + wr) * M + wc;
    const float* p2p = P2 + (size_t)b * M + wc;
    const float* q2p = Q2 + (size_t)b * M + wc;

    // MMA mapping: warp -> rows (wid&3)*16, cols (wid>>2)*128
    const int r0  = (wid & 3) * 16;
    const int cbq = (wid >> 2) * 128;
    const __half* aAddr0 = &sW[(r0 + (lane & 15)) * 40 + (lane >> 4) * 8];
    const __half* aAddr1 = aAddr0 + 16;
    const int bRowOff = (lane & 15) * 264 + cbq + (lane >> 4) * 8;

    __syncthreads();
    const float P1r = sP1[wr];
    const float Q1r = sQ1[wr];

    for (int m0 = 0; m0 < M; m0 += 32) {
        // ---- load g chunk; one row = 256 halves = 32 uint4 ----
        const size_t gstep = (size_t)m0 * 32;
#pragma unroll
        for (int j = 0; j < 4; ++j) {
            sbh[j] = ghp[gstep + j];
        }

        // ---- w tile: fp32 compute, one fp16 rounding ----
        {
            unsigned short us[8];
            float ssum = 0.f;
            float cnt = 0.f;
#pragma unroll
            for (int j = 0; j < 2; ++j) {
                int4 a4 = *(const int4*)(adjp + m0 + j * 4);
                float4 p4 = *(const float4*)(p2p + m0 + j * 4);
                float4 q4 = *(const float4*)(q2p + m0 + j * 4);
                int av[4] = {a4.x, a4.y, a4.z, a4.w};
                float pv[4] = {p4.x, p4.y, p4.z, p4.w};
                float qv[4] = {q4.x, q4.y, q4.z, q4.w};
#pragma unroll
                for (int q = 0; q < 4; ++q) {
                    float w = fmaxf(P1r * pv[q], Q1r * qv[q]);
                    __half hw = __float2half_rn(w);
                    bool on = av[q] > 0;
                    unsigned short u = on ? __half_as_ushort(hw) : (unsigned short)0;
                    us[j * 4 + q] = u;
                    if (on) { ssum += __half2float(hw); cnt += 1.f; }
                }
            }
            uint4 v;
            v.x = (uint32_t)us[0] | ((uint32_t)us[1] << 16);
            v.y = (uint32_t)us[2] | ((uint32_t)us[3] << 16);
            v.z = (uint32_t)us[4] | ((uint32_t)us[5] << 16);
            v.w = (uint32_t)us[6] | ((uint32_t)us[7] << 16);
            *(uint4*)&sW[wr * 40 + wc] = v;
            ssum += __shfl_xor_sync(0xffffffffu, ssum, 1);
            ssum += __shfl_xor_sync(0xffffffffu, ssum, 2);
            cnt  += __shfl_xor_sync(0xffffffffu, cnt, 1);
            cnt  += __shfl_xor_sync(0xffffffffu, cnt, 2);
            if ((t & 3) == 0) { sSum[wr] += ssum; sDeg[wr] += cnt; }
        }
        __syncthreads();

        // ---- MMA over this chunk (g hi only) ----
        uint32_t afr[2][4];
        ldsm4(afr[0], aAddr0);
        ldsm4(afr[1], aAddr1);
#pragma unroll
        for (int kk = 0; kk < 2; ++kk) {
#pragma unroll
            for (int nb = 0; nb < 8; ++nb) {
                uint32_t bh[4];
                ldsm4t(bh, &sBhi[kk * 16 * 264 + bRowOff + nb * 16]);
                mma16816(c[nb * 2],     afr[kk], bh[0], bh[1]);
                mma16816(c[nb * 2 + 1], afr[kk], bh[2], bh[3]);
            }
        }
        __syncthreads();
    }

    // ---- epilogue ----
    const int rlo = r0 + (lane >> 2);
    const int rhi = rlo + 8;
    float slo = (sDeg[rlo] > 0.f && sSum[rlo] > 0.f) ? sDeg[rlo] / sSum[rlo] : 0.f;
    float shi = (sDeg[rhi] > 0.f && sSum[rhi] > 0.f) ? sDeg[rhi] / sSum[rhi] : 0.f;
    float* olo = out + ((size_t)b * N + n0 + rlo) * 256;
    float* ohi = out + ((size_t)b * N + n0 + rhi) * 256;
#pragma unroll
    for (int j = 0; j < 16; ++j) {
        int col = cbq + (j >> 1) * 16 + (j & 1) * 8 + (lane & 3) * 2;
        float b0 = bias[col], b1 = bias[col + 1];
        float2 v0 = make_float2(c[j][0] * slo + b0, c[j][1] * slo + b1);
        float2 v1 = make_float2(c[j][2] * shi + b0, c[j][3] * shi + b1);
        *(float2*)(olo + col) = v0;
        *(float2*)(ohi + col) = v1;
    }
}

// ---------------------------------------------------------------------------
// Launch
// ---------------------------------------------------------------------------
extern "C" void kernel_launch(void* const* d_in, const int* in_sizes, int n_in,
                              void* d_out, int out_size)
{
    const float* x0   = (const float*)d_in[0];
    const float* x1   = (const float*)d_in[1];
    const float* W0   = (const float*)d_in[2];
    const float* W1   = (const float*)d_in[3];
    const float* a1_0 = (const float*)d_in[4];
    const float* a2_0 = (const float*)d_in[5];
    const float* a1_1 = (const float*)d_in[6];
    const float* a2_1 = (const float*)d_in[7];
    const float* bias = (const float*)d_in[8];
    const int* adj00  = (const int*)d_in[9];
    const int* adj01  = (const int*)d_in[10];
    const int* adj10  = (const int*)d_in[11];
    const int* adj11  = (const int*)d_in[12];
    float* out = (float*)d_out;

    __half *h0hi, *h0lo, *h1hi, *h1lo;
    float *eA, *eB, *eC, *eD, *eE, *eF, *mx, *P2, *Q2;
    cudaGetSymbolAddress((void**)&h0hi, g_h0hi);
    cudaGetSymbolAddress((void**)&h0lo, g_h0lo);
    cudaGetSymbolAddress((void**)&h1hi, g_h1hi);
    cudaGetSymbolAddress((void**)&h1lo, g_h1lo);
    cudaGetSymbolAddress((void**)&eA, g_eA);
    cudaGetSymbolAddress((void**)&eB, g_eB);
    cudaGetSymbolAddress((void**)&eC, g_eC);
    cudaGetSymbolAddress((void**)&eD, g_eD);
    cudaGetSymbolAddress((void**)&eE, g_eE);
    cudaGetSymbolAddress((void**)&eF, g_eF);
    cudaGetSymbolAddress((void**)&mx, g_mx);
    cudaGetSymbolAddress((void**)&P2, g_P2);
    cudaGetSymbolAddress((void**)&Q2, g_Q2);

    const int R0 = BATCH * N1;
    const int R1 = BATCH * N2;

    // P2/Q2 segment offsets per attention block (col sides: eB,eC,eE,eF)
    const size_t o0 = 0;
    const size_t o1 = (size_t)BATCH * N1;
    const size_t o2 = o1 + (size_t)BATCH * N2;
    const size_t o3 = o2 + (size_t)BATCH * N1;

    gemm_mma<<<dim3(R0 / 128, 2), 256>>>(x0, W0, h0hi, h0lo, F0K);
    gemm_mma<<<dim3(R1 / 128, 2), 256>>>(x1, W1, h1hi, h1lo, F1K);

    edot3_kernel<<<R0 / 8, 256>>>(h0hi, h0lo, a1_0, a2_0, a2_1, eA, eB, eE);
    edot3_kernel<<<R1 / 8, 256>>>(h1hi, h1lo, a2_0, a1_1, a2_1, eC, eD, eF);

    bmax_kernel<<<BATCH, 256>>>(eB, mx + 0 * BATCH, N1);
    bmax_kernel<<<BATCH, 256>>>(eC, mx + 1 * BATCH, N2);
    bmax_kernel<<<BATCH, 256>>>(eE, mx + 2 * BATCH, N1);
    bmax_kernel<<<BATCH, 256>>>(eF, mx + 3 * BATCH, N2);

    pq_kernel<<<dim3(N1 / 256, BATCH), 256>>>(eB, mx + 0 * BATCH, P2 + o0, Q2 + o0, N1);
    pq_kernel<<<dim3(N2 / 256, BATCH), 256>>>(eC, mx + 1 * BATCH, P2 + o1, Q2 + o1, N2);
    pq_kernel<<<dim3(N1 / 256, BATCH), 256>>>(eE, mx + 2 * BATCH, P2 + o2, Q2 + o2, N1);
    pq_kernel<<<dim3(N2 / 256, BATCH), 256>>>(eF, mx + 3 * BATCH, P2 + o3, Q2 + o3, N2);

    float* o00 = out;
    float* o01 = out + (size_t)BATCH * N1 * 256;
    float* o10 = o01 + (size_t)BATCH * N1 * 256;
    float* o11 = o10 + (size_t)BATCH * N2 * 256;

    att_mma_kernel<<<dim3(N1 / 64, BATCH), 256>>>(
        h0hi, adj00, eA, mx + 0 * BATCH, P2 + o0, Q2 + o0, bias, o00, N1, N1);
    att_mma_kernel<<<dim3(N1 / 64, BATCH), 256>>>(
        h1hi, adj01, eA, mx + 1 * BATCH, P2 + o1, Q2 + o1, bias, o01, N1, N2);
    att_mma_kernel<<<dim3(N2 / 64, BATCH), 256>>>(
        h0hi, adj10, eD, mx + 2 * BATCH, P2 + o2, Q2 + o2, bias, o10, N2, N1);
    att_mma_kernel<<<dim3(N2 / 64, BATCH), 256>>>(
        h1hi, adj11, eD, mx + 3 * BATCH, P2 + o3, Q2 + o3, bias, o11, N2, N2);
}

// round 8
// speedup vs baseline: 3.4875x; 1.2983x over previous
#include <cuda_runtime.h>
#include <cuda_fp16.h>
#include <cstdint>
#include <cstddef>

#define BATCH 64
#define N1 1024
#define N2 512
#define F0K 512
#define F1K 384

// ---------------------------------------------------------------------------
// Scratch
// ---------------------------------------------------------------------------
__device__ __half g_h0hi[(size_t)BATCH * N1 * 256];
__device__ __half g_h0lo[(size_t)BATCH * N1 * 256];
__device__ __half g_h1hi[(size_t)BATCH * N2 * 256];
__device__ __half g_h1lo[(size_t)BATCH * N2 * 256];
__device__ float g_eA[BATCH * N1];
__device__ float g_eB[BATCH * N1];
__device__ float g_eC[BATCH * N2];
__device__ float g_eD[BATCH * N2];
__device__ float g_eE[BATCH * N1];
__device__ float g_eF[BATCH * N2];
__device__ float g_mx[4 * BATCH];
__device__ float g_P2[2 * BATCH * (N1 + N2)];
__device__ float g_Q2[2 * BATCH * (N1 + N2)];

// ---------------------------------------------------------------------------
// mma.sync / ldmatrix / cp.async helpers (sm_80 PTX, valid at base sm_103)
// ---------------------------------------------------------------------------
__device__ __forceinline__ void ldsm4(uint32_t* d, const void* p) {
    uint32_t a = (uint32_t)__cvta_generic_to_shared(p);
    asm volatile("ldmatrix.sync.aligned.m8n8.x4.shared.b16 {%0,%1,%2,%3}, [%4];"
                 : "=r"(d[0]), "=r"(d[1]), "=r"(d[2]), "=r"(d[3]) : "r"(a));
}
__device__ __forceinline__ void ldsm4t(uint32_t* d, const void* p) {
    uint32_t a = (uint32_t)__cvta_generic_to_shared(p);
    asm volatile("ldmatrix.sync.aligned.m8n8.x4.trans.shared.b16 {%0,%1,%2,%3}, [%4];"
                 : "=r"(d[0]), "=r"(d[1]), "=r"(d[2]), "=r"(d[3]) : "r"(a));
}
__device__ __forceinline__ void mma16816(float* c, const uint32_t* a,
                                         uint32_t b0, uint32_t b1) {
    asm volatile(
        "mma.sync.aligned.m16n8k16.row.col.f32.f16.f16.f32 "
        "{%0,%1,%2,%3}, {%4,%5,%6,%7}, {%8,%9}, {%0,%1,%2,%3};"
        : "+f"(c[0]), "+f"(c[1]), "+f"(c[2]), "+f"(c[3])
        : "r"(a[0]), "r"(a[1]), "r"(a[2]), "r"(a[3]), "r"(b0), "r"(b1));
}
__device__ __forceinline__ void cp16(uint32_t dst, const void* src) {
    asm volatile("cp.async.cg.shared.global [%0], [%1], 16;"
                 :: "r"(dst), "l"(src));
}
#define CP_COMMIT() asm volatile("cp.async.commit_group;" ::: "memory")
#define CP_WAIT0()  asm volatile("cp.async.wait_group 0;" ::: "memory")

// w-gen for 8 neighbors: returns packed fp16 weights + row-partial sums
struct W8 { uint4 v; float ssum; float cnt; };
__device__ __forceinline__ W8 wgen8(
    int4 a0, int4 a1, float4 p0, float4 p1, float4 q0, float4 q1,
    float P1r, float Q1r)
{
    int   av[8] = {a0.x, a0.y, a0.z, a0.w, a1.x, a1.y, a1.z, a1.w};
    float pv[8] = {p0.x, p0.y, p0.z, p0.w, p1.x, p1.y, p1.z, p1.w};
    float qv[8] = {q0.x, q0.y, q0.z, q0.w, q1.x, q1.y, q1.z, q1.w};
    unsigned short us[8];
    W8 r; r.ssum = 0.f; r.cnt = 0.f;
#pragma unroll
    for (int q = 0; q < 8; ++q) {
        float w = fmaxf(P1r * pv[q], Q1r * qv[q]);
        __half hw = __float2half_rn(w);
        bool on = av[q] > 0;
        us[q] = on ? __half_as_ushort(hw) : (unsigned short)0;
        if (on) { r.ssum += __half2float(hw); r.cnt += 1.f; }
    }
    r.v.x = (uint32_t)us[0] | ((uint32_t)us[1] << 16);
    r.v.y = (uint32_t)us[2] | ((uint32_t)us[3] << 16);
    r.v.z = (uint32_t)us[4] | ((uint32_t)us[5] << 16);
    r.v.w = (uint32_t)us[6] | ((uint32_t)us[7] << 16);
    return r;
}

// ---------------------------------------------------------------------------
// Tensor-core GEMM: C[rows,256] = A[rows,K] @ W[K,256]
// fp16 hi/lo split of BOTH operands, 3 MMA passes; pipelined global loads.
// ---------------------------------------------------------------------------
__global__ __launch_bounds__(256) void gemm_mma(
    const float* __restrict__ A, const float* __restrict__ W,
    __half* __restrict__ Chi, __half* __restrict__ Clo, int K)
{
    __shared__ __align__(16) __half sAhi[128 * 40];
    __shared__ __align__(16) __half sAlo[128 * 40];
    __shared__ __align__(16) __half sWhi[32 * 136];
    __shared__ __align__(16) __half sWlo[32 * 136];

    const int t   = threadIdx.x;
    const int lane = t & 31;
    const int wid  = t >> 5;
    const int m0  = blockIdx.x * 128;
    const int nc0 = blockIdx.y * 128;

    const int ar = t >> 1;
    const int ac = (t & 1) * 16;
    const float* Ap = A + (size_t)(m0 + ar) * K + ac;
    const int wk = t >> 3;
    const int wc = (t & 7) * 16;
    const float* Wp = W + (size_t)wk * 256 + nc0 + wc;

    const int am0 = (wid & 3) * 32;
    const int cn0 = (wid >> 2) * 64;

    float cf[16][4];
#pragma unroll
    for (int i = 0; i < 16; ++i)
#pragma unroll
        for (int j = 0; j < 4; ++j) cf[i][j] = 0.f;

    // prefetch k0 = 0
    float4 avr[4], wvr[4];
#pragma unroll
    for (int j = 0; j < 4; ++j) {
        avr[j] = *(const float4*)(Ap + j * 4);
        wvr[j] = *(const float4*)(Wp + j * 4);
    }

    for (int k0 = 0; k0 < K; k0 += 32) {
        // ---- convert + store staged regs ----
#pragma unroll
        for (int j = 0; j < 4; ++j) {
            float4 v = avr[j];
            __half2 h0 = __floats2half2_rn(v.x, v.y);
            __half2 h1 = __floats2half2_rn(v.z, v.w);
            __half2 l0 = __floats2half2_rn(v.x - __low2float(h0), v.y - __high2float(h0));
            __half2 l1 = __floats2half2_rn(v.z - __low2float(h1), v.w - __high2float(h1));
            int off = ar * 40 + ac + j * 4;
            *(__half2*)&sAhi[off]     = h0;
            *(__half2*)&sAhi[off + 2] = h1;
            *(__half2*)&sAlo[off]     = l0;
            *(__half2*)&sAlo[off + 2] = l1;
            v = wvr[j];
            h0 = __floats2half2_rn(v.x, v.y);
            h1 = __floats2half2_rn(v.z, v.w);
            l0 = __floats2half2_rn(v.x - __low2float(h0), v.y - __high2float(h0));
            l1 = __floats2half2_rn(v.z - __low2float(h1), v.w - __high2float(h1));
            off = wk * 136 + wc + j * 4;
            *(__half2*)&sWhi[off]     = h0;
            *(__half2*)&sWhi[off + 2] = h1;
            *(__half2*)&sWlo[off]     = l0;
            *(__half2*)&sWlo[off + 2] = l1;
        }
        __syncthreads();

        // ---- prefetch next chunk (hidden behind MMA below) ----
        if (k0 + 32 < K) {
#pragma unroll
            for (int j = 0; j < 4; ++j) {
                avr[j] = *(const float4*)(Ap + k0 + 32 + j * 4);
                wvr[j] = *(const float4*)(Wp + (size_t)(k0 + 32) * 256 + j * 4);
            }
        }

        // ---- MMA: 2 k-steps, 2 m-tiles, 4 n16-groups, 3 passes ----
#pragma unroll
        for (int kk = 0; kk < 2; ++kk) {
#pragma unroll
            for (int mt = 0; mt < 2; ++mt) {
                uint32_t ah[4], al[4];
                const int arow = am0 + mt * 16 + (lane & 15);
                const int acol = kk * 16 + (lane >> 4) * 8;
                ldsm4(ah, &sAhi[arow * 40 + acol]);
                ldsm4(al, &sAlo[arow * 40 + acol]);
#pragma unroll
                for (int nt = 0; nt < 4; ++nt) {
                    uint32_t bh[4], bl[4];
                    const int boff = (kk * 16 + (lane & 15)) * 136 + cn0 +
                                     nt * 16 + (lane >> 4) * 8;
                    ldsm4t(bh, &sWhi[boff]);
                    ldsm4t(bl, &sWlo[boff]);
                    float* c0 = cf[mt * 8 + nt * 2];
                    float* c1 = cf[mt * 8 + nt * 2 + 1];
                    mma16816(c0, ah, bh[0], bh[1]);
                    mma16816(c1, ah, bh[2], bh[3]);
                    mma16816(c0, ah, bl[0], bl[1]);
                    mma16816(c1, ah, bl[2], bl[3]);
                    mma16816(c0, al, bh[0], bh[1]);
                    mma16816(c1, al, bh[2], bh[3]);
                }
            }
        }
        __syncthreads();
    }

    // ---- epilogue: fp32 acc -> fp16 hi/lo ----
    const int rlo = am0 + (lane >> 2);
#pragma unroll
    for (int mt = 0; mt < 2; ++mt) {
#pragma unroll
        for (int j = 0; j < 8; ++j) {
            int nt = j >> 1;
            int half8 = j & 1;
            float* cc = cf[mt * 8 + j];
            int row = rlo + mt * 16;
            int col = nc0 + cn0 + nt * 16 + half8 * 8 + (lane & 3) * 2;
            {
                float x = cc[0], y = cc[1];
                __half2 hi = __floats2half2_rn(x, y);
                __half2 lo = __floats2half2_rn(x - __low2float(hi), y - __high2float(hi));
                size_t off = (size_t)(m0 + row) * 256 + col;
                *(__half2*)&Chi[off] = hi;
                *(__half2*)&Clo[off] = lo;
            }
            {
                float x = cc[2], y = cc[3];
                __half2 hi = __floats2half2_rn(x, y);
                __half2 lo = __floats2half2_rn(x - __low2float(hi), y - __high2float(hi));
                size_t off = (size_t)(m0 + row + 8) * 256 + col;
                *(__half2*)&Chi[off] = hi;
                *(__half2*)&Clo[off] = lo;
            }
        }
    }
}

// ---------------------------------------------------------------------------
// e_k = h . a_k for 3 vectors, h = hi + lo
// ---------------------------------------------------------------------------
__global__ __launch_bounds__(256) void edot3_kernel(
    const __half* __restrict__ hhi, const __half* __restrict__ hlo,
    const float* __restrict__ a0, const float* __restrict__ a1,
    const float* __restrict__ a2,
    float* __restrict__ e0, float* __restrict__ e1, float* __restrict__ e2)
{
    const int r = blockIdx.x * 8 + (threadIdx.x >> 5);
    const int lane = threadIdx.x & 31;
    const __half* ph = hhi + (size_t)r * 256;
    const __half* pl = hlo + (size_t)r * 256;
    float s0 = 0.f, s1 = 0.f, s2 = 0.f;
#pragma unroll
    for (int i = 0; i < 8; ++i) {
        int c = lane + i * 32;
        float x = __half2float(ph[c]) + __half2float(pl[c]);
        s0 += x * a0[c];
        s1 += x * a1[c];
        s2 += x * a2[c];
    }
#pragma unroll
    for (int o = 16; o > 0; o >>= 1) {
        s0 += __shfl_xor_sync(0xffffffffu, s0, o);
        s1 += __shfl_xor_sync(0xffffffffu, s1, o);
        s2 += __shfl_xor_sync(0xffffffffu, s2, o);
    }
    if (lane == 0) { e0[r] = s0; e1[r] = s1; e2[r] = s2; }
}

// Per-batch max of e2
__global__ __launch_bounds__(256) void bmax_kernel(
    const float* __restrict__ e2, float* __restrict__ mx, int M)
{
    __shared__ float red[256];
    const int b = blockIdx.x;
    const int t = threadIdx.x;
    const float* p = e2 + (size_t)b * M;
    float m = -3.4e38f;
    for (int i = t; i < M; i += 256) m = fmaxf(m, p[i]);
    red[t] = m;
    __syncthreads();
    for (int s = 128; s > 0; s >>= 1) {
        if (t < s) red[t] = fmaxf(red[t], red[t + s]);
        __syncthreads();
    }
    if (t == 0) mx[b] = red[0];
}

// P2 = exp(e2 - mx), Q2 = exp(0.2*(e2 - mx))
__global__ __launch_bounds__(256) void pq_kernel(
    const float* __restrict__ e2, const float* __restrict__ mx,
    float* __restrict__ P2, float* __restrict__ Q2, int M)
{
    const int b = blockIdx.y;
    const int i = blockIdx.x * 256 + threadIdx.x;
    float d = e2[(size_t)b * M + i] - mx[b];
    P2[(size_t)b * M + i] = __expf(d);
    Q2[(size_t)b * M + i] = __expf(0.2f * d);
}

// ---------------------------------------------------------------------------
// Fused masked attention on tensor cores, software-pipelined (ping-pong smem)
// CTA: 64 rows x 256 cols, K-chunk 32 neighbors. g in plain fp16.
// ---------------------------------------------------------------------------
__global__ __launch_bounds__(256, 2) void att_mma_kernel(
    const __half* __restrict__ ghi,
    const int* __restrict__ adj,
    const float* __restrict__ e1, const float* __restrict__ mx,
    const float* __restrict__ P2, const float* __restrict__ Q2,
    const float* __restrict__ bias,
    float* __restrict__ out, int N, int M)
{
    __shared__ __align__(16) __half sW[2][64 * 40];
    __shared__ __align__(16) __half sB[2][32 * 264];
    __shared__ float sP1[64], sQ1[64], sSum[64], sDeg[64];

    const int t    = threadIdx.x;
    const int lane = t & 31;
    const int wid  = t >> 5;
    const int b    = blockIdx.y;
    const int n0   = blockIdx.x * 64;

    if (t < 64) {
        float v = e1[(size_t)b * N + n0 + t] + mx[b];
        float sh = fmaxf(v, 0.2f * v);
        sP1[t] = __expf(v - sh);
        sQ1[t] = __expf(0.2f * v - sh);
        sSum[t] = 0.f;
        sDeg[t] = 0.f;
    }
    __syncthreads();

    float c[16][4];
#pragma unroll
    for (int i = 0; i < 16; ++i)
#pragma unroll
        for (int j = 0; j < 4; ++j) c[i][j] = 0.f;

    // g tile cp.async mapping: row k = t>>3, cols (t&7)*32 .. +31 (64B)
    const int bk = t >> 3;
    const int bc = (t & 7) * 32;
    const __half* gsrc = ghi + ((size_t)b * M + bk) * 256 + bc;
    const uint32_t sb0 = (uint32_t)__cvta_generic_to_shared(&sB[0][bk * 264 + bc]);
    const uint32_t sb1 = (uint32_t)__cvta_generic_to_shared(&sB[1][bk * 264 + bc]);

    // w-gen mapping: row r = t>>2, cols (t&3)*8 .. +7
    const int wr = t >> 2;
    const int wc = (t & 3) * 8;
    const int* adjp = adj + ((size_t)b * N + n0 + wr) * M + wc;
    const float* p2p = P2 + (size_t)b * M + wc;
    const float* q2p = Q2 + (size_t)b * M + wc;
    const float P1r = sP1[wr];
    const float Q1r = sQ1[wr];

    // MMA mapping: warp -> rows (wid&3)*16, cols (wid>>2)*128
    const int r0  = (wid & 3) * 16;
    const int cbq = (wid >> 2) * 128;
    const int aOff = (r0 + (lane & 15)) * 40 + (lane >> 4) * 8;
    const int bRowOff = (lane & 15) * 264 + cbq + (lane >> 4) * 8;

    const int iters = M >> 5;

    // ---- prolog: stage chunk 0 into buffer 0 ----
    {
#pragma unroll
        for (int j = 0; j < 4; ++j) cp16(sb0 + j * 16, gsrc + j * 8);
        CP_COMMIT();
        int4 a0 = *(const int4*)(adjp);
        int4 a1 = *(const int4*)(adjp + 4);
        float4 p0 = *(const float4*)(p2p);
        float4 p1 = *(const float4*)(p2p + 4);
        float4 q0 = *(const float4*)(q2p);
        float4 q1 = *(const float4*)(q2p + 4);
        W8 w = wgen8(a0, a1, p0, p1, q0, q1, P1r, Q1r);
        *(uint4*)&sW[0][wr * 40 + wc] = w.v;
        float ssum = w.ssum, cnt = w.cnt;
        ssum += __shfl_xor_sync(0xffffffffu, ssum, 1);
        ssum += __shfl_xor_sync(0xffffffffu, ssum, 2);
        cnt  += __shfl_xor_sync(0xffffffffu, cnt, 1);
        cnt  += __shfl_xor_sync(0xffffffffu, cnt, 2);
        if ((t & 3) == 0) { sSum[wr] += ssum; sDeg[wr] += cnt; }
        CP_WAIT0();
    }
    __syncthreads();

    for (int it = 0; it < iters; ++it) {
        const int cur = it & 1;
        const int nxt = cur ^ 1;
        const bool hasNext = (it + 1) < iters;
        int4 a0, a1; float4 p0, p1, q0, q1;

        if (hasNext) {
            const int m1 = (it + 1) * 32;
            const uint32_t sbn = nxt ? sb1 : sb0;
#pragma unroll
            for (int j = 0; j < 4; ++j)
                cp16(sbn + j * 16, gsrc + (size_t)m1 * 256 + j * 8);
            CP_COMMIT();
            a0 = *(const int4*)(adjp + m1);
            a1 = *(const int4*)(adjp + m1 + 4);
            p0 = *(const float4*)(p2p + m1);
            p1 = *(const float4*)(p2p + m1 + 4);
            q0 = *(const float4*)(q2p + m1);
            q1 = *(const float4*)(q2p + m1 + 4);
        }

        // ---- MMA from buffer cur ----
        {
            const __half* wbase = &sW[cur][0];
            const __half* bbase = &sB[cur][0];
            uint32_t afr[2][4];
            ldsm4(afr[0], wbase + aOff);
            ldsm4(afr[1], wbase + aOff + 16);
#pragma unroll
            for (int kk = 0; kk < 2; ++kk) {
#pragma unroll
                for (int nb = 0; nb < 8; ++nb) {
                    uint32_t bh[4];
                    ldsm4t(bh, bbase + kk * 16 * 264 + bRowOff + nb * 16);
                    mma16816(c[nb * 2],     afr[kk], bh[0], bh[1]);
                    mma16816(c[nb * 2 + 1], afr[kk], bh[2], bh[3]);
                }
            }
        }

        if (hasNext) {
            W8 w = wgen8(a0, a1, p0, p1, q0, q1, P1r, Q1r);
            *(uint4*)&sW[nxt][wr * 40 + wc] = w.v;
            float ssum = w.ssum, cnt = w.cnt;
            ssum += __shfl_xor_sync(0xffffffffu, ssum, 1);
            ssum += __shfl_xor_sync(0xffffffffu, ssum, 2);
            cnt  += __shfl_xor_sync(0xffffffffu, cnt, 1);
            cnt  += __shfl_xor_sync(0xffffffffu, cnt, 2);
            if ((t & 3) == 0) { sSum[wr] += ssum; sDeg[wr] += cnt; }
            CP_WAIT0();
        }
        __syncthreads();
    }

    // ---- epilogue ----
    const int rlo = r0 + (lane >> 2);
    const int rhi = rlo + 8;
    float slo = (sDeg[rlo] > 0.f && sSum[rlo] > 0.f) ? sDeg[rlo] / sSum[rlo] : 0.f;
    float shi = (sDeg[rhi] > 0.f && sSum[rhi] > 0.f) ? sDeg[rhi] / sSum[rhi] : 0.f;
    float* olo = out + ((size_t)b * N + n0 + rlo) * 256;
    float* ohi = out + ((size_t)b * N + n0 + rhi) * 256;
#pragma unroll
    for (int j = 0; j < 16; ++j) {
        int col = cbq + (j >> 1) * 16 + (j & 1) * 8 + (lane & 3) * 2;
        float b0 = bias[col], b1 = bias[col + 1];
        float2 v0 = make_float2(c[j][0] * slo + b0, c[j][1] * slo + b1);
        float2 v1 = make_float2(c[j][2] * shi + b0, c[j][3] * shi + b1);
        *(float2*)(olo + col) = v0;
        *(float2*)(ohi + col) = v1;
    }
}

// ---------------------------------------------------------------------------
// Launch
// ---------------------------------------------------------------------------
extern "C" void kernel_launch(void* const* d_in, const int* in_sizes, int n_in,
                              void* d_out, int out_size)
{
    const float* x0   = (const float*)d_in[0];
    const float* x1   = (const float*)d_in[1];
    const float* W0   = (const float*)d_in[2];
    const float* W1   = (const float*)d_in[3];
    const float* a1_0 = (const float*)d_in[4];
    const float* a2_0 = (const float*)d_in[5];
    const float* a1_1 = (const float*)d_in[6];
    const float* a2_1 = (const float*)d_in[7];
    const float* bias = (const float*)d_in[8];
    const int* adj00  = (const int*)d_in[9];
    const int* adj01  = (const int*)d_in[10];
    const int* adj10  = (const int*)d_in[11];
    const int* adj11  = (const int*)d_in[12];
    float* out = (float*)d_out;

    __half *h0hi, *h0lo, *h1hi, *h1lo;
    float *eA, *eB, *eC, *eD, *eE, *eF, *mx, *P2, *Q2;
    cudaGetSymbolAddress((void**)&h0hi, g_h0hi);
    cudaGetSymbolAddress((void**)&h0lo, g_h0lo);
    cudaGetSymbolAddress((void**)&h1hi, g_h1hi);
    cudaGetSymbolAddress((void**)&h1lo, g_h1lo);
    cudaGetSymbolAddress((void**)&eA, g_eA);
    cudaGetSymbolAddress((void**)&eB, g_eB);
    cudaGetSymbolAddress((void**)&eC, g_eC);
    cudaGetSymbolAddress((void**)&eD, g_eD);
    cudaGetSymbolAddress((void**)&eE, g_eE);
    cudaGetSymbolAddress((void**)&eF, g_eF);
    cudaGetSymbolAddress((void**)&mx, g_mx);
    cudaGetSymbolAddress((void**)&P2, g_P2);
    cudaGetSymbolAddress((void**)&Q2, g_Q2);

    const int R0 = BATCH * N1;
    const int R1 = BATCH * N2;

    const size_t o0 = 0;
    const size_t o1 = (size_t)BATCH * N1;
    const size_t o2 = o1 + (size_t)BATCH * N2;
    const size_t o3 = o2 + (size_t)BATCH * N1;

    gemm_mma<<<dim3(R0 / 128, 2), 256>>>(x0, W0, h0hi, h0lo, F0K);
    gemm_mma<<<dim3(R1 / 128, 2), 256>>>(x1, W1, h1hi, h1lo, F1K);

    edot3_kernel<<<R0 / 8, 256>>>(h0hi, h0lo, a1_0, a2_0, a2_1, eA, eB, eE);
    edot3_kernel<<<R1 / 8, 256>>>(h1hi, h1lo, a2_0, a1_1, a2_1, eC, eD, eF);

    bmax_kernel<<<BATCH, 256>>>(eB, mx + 0 * BATCH, N1);
    bmax_kernel<<<BATCH, 256>>>(eC, mx + 1 * BATCH, N2);
    bmax_kernel<<<BATCH, 256>>>(eE, mx + 2 * BATCH, N1);
    bmax_kernel<<<BATCH, 256>>>(eF, mx + 3 * BATCH, N2);

    pq_kernel<<<dim3(N1 / 256, BATCH), 256>>>(eB, mx + 0 * BATCH, P2 + o0, Q2 + o0, N1);
    pq_kernel<<<dim3(N2 / 256, BATCH), 256>>>(eC, mx + 1 * BATCH, P2 + o1, Q2 + o1, N2);
    pq_kernel<<<dim3(N1 / 256, BATCH), 256>>>(eE, mx + 2 * BATCH, P2 + o2, Q2 + o2, N1);
    pq_kernel<<<dim3(N2 / 256, BATCH), 256>>>(eF, mx + 3 * BATCH, P2 + o3, Q2 + o3, N2);

    float* o00 = out;
    float* o01 = out + (size_t)BATCH * N1 * 256;
    float* o10 = o01 + (size_t)BATCH * N1 * 256;
    float* o11 = o10 + (size_t)BATCH * N2 * 256;

    att_mma_kernel<<<dim3(N1 / 64, BATCH), 256>>>(
        h0hi, adj00, eA, mx + 0 * BATCH, P2 + o0, Q2 + o0, bias, o00, N1, N1);
    att_mma_kernel<<<dim3(N1 / 64, BATCH), 256>>>(
        h1hi, adj01, eA, mx + 1 * BATCH, P2 + o1, Q2 + o1, bias, o01, N1, N2);
    att_mma_kernel<<<dim3(N2 / 64, BATCH), 256>>>(
        h0hi, adj10, eD, mx + 2 * BATCH, P2 + o2, Q2 + o2, bias, o10, N2, N1);
    att_mma_kernel<<<dim3(N2 / 64, BATCH), 256>>>(
        h1hi, adj11, eD, mx + 3 * BATCH, P2 + o3, Q2 + o3, bias, o11, N2, N2);
}

// round 9
// speedup vs baseline: 3.9442x; 1.1309x over previous
#include <cuda_runtime.h>
#include <cuda_fp16.h>
#include <cstdint>
#include <cstddef>

#define BATCH 64
#define N1 1024
#define N2 512
#define F0K 512
#define F1K 384

// ---------------------------------------------------------------------------
// Scratch
// ---------------------------------------------------------------------------
__device__ __half g_h0hi[(size_t)BATCH * N1 * 256];
__device__ __half g_h0lo[(size_t)BATCH * N1 * 256];
__device__ __half g_h1hi[(size_t)BATCH * N2 * 256];
__device__ __half g_h1lo[(size_t)BATCH * N2 * 256];
__device__ float g_eA[BATCH * N1];
__device__ float g_eB[BATCH * N1];
__device__ float g_eC[BATCH * N2];
__device__ float g_eD[BATCH * N2];
__device__ float g_eE[BATCH * N1];
__device__ float g_eF[BATCH * N2];
__device__ float g_mx[4 * BATCH];
__device__ float g_P2[2 * BATCH * (N1 + N2)];
__device__ float g_Q2[2 * BATCH * (N1 + N2)];

// P2/Q2 segment offsets (blk order: 00 -> eB(N1), 01 -> eC(N2), 10 -> eE(N1), 11 -> eF(N2))
#define PQ_O0 ((size_t)0)
#define PQ_O1 ((size_t)BATCH * N1)
#define PQ_O2 (PQ_O1 + (size_t)BATCH * N2)
#define PQ_O3 (PQ_O2 + (size_t)BATCH * N1)
// output segment offsets
#define OO_00 ((size_t)0)
#define OO_01 ((size_t)BATCH * N1 * 256)
#define OO_10 (OO_01 + (size_t)BATCH * N1 * 256)
#define OO_11 (OO_10 + (size_t)BATCH * N2 * 256)

// ---------------------------------------------------------------------------
// mma.sync / ldmatrix / cp.async helpers (sm_80 PTX, valid at base sm_103)
// ---------------------------------------------------------------------------
__device__ __forceinline__ void ldsm4(uint32_t* d, const void* p) {
    uint32_t a = (uint32_t)__cvta_generic_to_shared(p);
    asm volatile("ldmatrix.sync.aligned.m8n8.x4.shared.b16 {%0,%1,%2,%3}, [%4];"
                 : "=r"(d[0]), "=r"(d[1]), "=r"(d[2]), "=r"(d[3]) : "r"(a));
}
__device__ __forceinline__ void ldsm4t(uint32_t* d, const void* p) {
    uint32_t a = (uint32_t)__cvta_generic_to_shared(p);
    asm volatile("ldmatrix.sync.aligned.m8n8.x4.trans.shared.b16 {%0,%1,%2,%3}, [%4];"
                 : "=r"(d[0]), "=r"(d[1]), "=r"(d[2]), "=r"(d[3]) : "r"(a));
}
__device__ __forceinline__ void mma16816(float* c, const uint32_t* a,
                                         uint32_t b0, uint32_t b1) {
    asm volatile(
        "mma.sync.aligned.m16n8k16.row.col.f32.f16.f16.f32 "
        "{%0,%1,%2,%3}, {%4,%5,%6,%7}, {%8,%9}, {%0,%1,%2,%3};"
        : "+f"(c[0]), "+f"(c[1]), "+f"(c[2]), "+f"(c[3])
        : "r"(a[0]), "r"(a[1]), "r"(a[2]), "r"(a[3]), "r"(b0), "r"(b1));
}
__device__ __forceinline__ void cp16(uint32_t dst, const void* src) {
    asm volatile("cp.async.cg.shared.global [%0], [%1], 16;"
                 :: "r"(dst), "l"(src));
}
#define CP_COMMIT() asm volatile("cp.async.commit_group;" ::: "memory")
#define CP_WAIT0()  asm volatile("cp.async.wait_group 0;" ::: "memory")

// w-gen for 8 neighbors: packed fp16 weights + row-partial sums
struct W8 { uint4 v; float ssum; float cnt; };
__device__ __forceinline__ W8 wgen8(
    int4 a0, int4 a1, float4 p0, float4 p1, float4 q0, float4 q1,
    float P1r, float Q1r)
{
    int   av[8] = {a0.x, a0.y, a0.z, a0.w, a1.x, a1.y, a1.z, a1.w};
    float pv[8] = {p0.x, p0.y, p0.z, p0.w, p1.x, p1.y, p1.z, p1.w};
    float qv[8] = {q0.x, q0.y, q0.z, q0.w, q1.x, q1.y, q1.z, q1.w};
    unsigned short us[8];
    W8 r; r.ssum = 0.f; r.cnt = 0.f;
#pragma unroll
    for (int q = 0; q < 8; ++q) {
        float w = fmaxf(P1r * pv[q], Q1r * qv[q]);
        __half hw = __float2half_rn(w);
        bool on = av[q] > 0;
        us[q] = on ? __half_as_ushort(hw) : (unsigned short)0;
        if (on) { r.ssum += __half2float(hw); r.cnt += 1.f; }
    }
    r.v.x = (uint32_t)us[0] | ((uint32_t)us[1] << 16);
    r.v.y = (uint32_t)us[2] | ((uint32_t)us[3] << 16);
    r.v.z = (uint32_t)us[4] | ((uint32_t)us[5] << 16);
    r.v.w = (uint32_t)us[6] | ((uint32_t)us[7] << 16);
    return r;
}

// ---------------------------------------------------------------------------
// Merged tensor-core GEMM for both inputs (segment decoded from blockIdx.x)
// ---------------------------------------------------------------------------
__global__ __launch_bounds__(256) void gemm_all(
    const float* __restrict__ x0, const float* __restrict__ x1,
    const float* __restrict__ W0, const float* __restrict__ W1)
{
    __shared__ __align__(16) __half sAhi[128 * 40];
    __shared__ __align__(16) __half sAlo[128 * 40];
    __shared__ __align__(16) __half sWhi[32 * 136];
    __shared__ __align__(16) __half sWlo[32 * 136];

    const int bx = blockIdx.x;
    const float* A; const float* W; __half* Chi; __half* Clo; int K, mblk;
    if (bx < BATCH * N1 / 128) {
        A = x0; W = W0; K = F0K; mblk = bx;
        Chi = g_h0hi; Clo = g_h0lo;
    } else {
        A = x1; W = W1; K = F1K; mblk = bx - BATCH * N1 / 128;
        Chi = g_h1hi; Clo = g_h1lo;
    }

    const int t    = threadIdx.x;
    const int lane = t & 31;
    const int wid  = t >> 5;
    const int m0   = mblk * 128;
    const int nc0  = blockIdx.y * 128;

    const int ar = t >> 1;
    const int ac = (t & 1) * 16;
    const float* Ap = A + (size_t)(m0 + ar) * K + ac;
    const int wk = t >> 3;
    const int wc = (t & 7) * 16;
    const float* Wp = W + (size_t)wk * 256 + nc0 + wc;

    const int am0 = (wid & 3) * 32;
    const int cn0 = (wid >> 2) * 64;

    float cf[16][4];
#pragma unroll
    for (int i = 0; i < 16; ++i)
#pragma unroll
        for (int j = 0; j < 4; ++j) cf[i][j] = 0.f;

    float4 avr[4], wvr[4];
#pragma unroll
    for (int j = 0; j < 4; ++j) {
        avr[j] = *(const float4*)(Ap + j * 4);
        wvr[j] = *(const float4*)(Wp + j * 4);
    }

    for (int k0 = 0; k0 < K; k0 += 32) {
#pragma unroll
        for (int j = 0; j < 4; ++j) {
            float4 v = avr[j];
            __half2 h0 = __floats2half2_rn(v.x, v.y);
            __half2 h1 = __floats2half2_rn(v.z, v.w);
            __half2 l0 = __floats2half2_rn(v.x - __low2float(h0), v.y - __high2float(h0));
            __half2 l1 = __floats2half2_rn(v.z - __low2float(h1), v.w - __high2float(h1));
            int off = ar * 40 + ac + j * 4;
            *(__half2*)&sAhi[off]     = h0;
            *(__half2*)&sAhi[off + 2] = h1;
            *(__half2*)&sAlo[off]     = l0;
            *(__half2*)&sAlo[off + 2] = l1;
            v = wvr[j];
            h0 = __floats2half2_rn(v.x, v.y);
            h1 = __floats2half2_rn(v.z, v.w);
            l0 = __floats2half2_rn(v.x - __low2float(h0), v.y - __high2float(h0));
            l1 = __floats2half2_rn(v.z - __low2float(h1), v.w - __high2float(h1));
            off = wk * 136 + wc + j * 4;
            *(__half2*)&sWhi[off]     = h0;
            *(__half2*)&sWhi[off + 2] = h1;
            *(__half2*)&sWlo[off]     = l0;
            *(__half2*)&sWlo[off + 2] = l1;
        }
        __syncthreads();

        if (k0 + 32 < K) {
#pragma unroll
            for (int j = 0; j < 4; ++j) {
                avr[j] = *(const float4*)(Ap + k0 + 32 + j * 4);
                wvr[j] = *(const float4*)(Wp + (size_t)(k0 + 32) * 256 + j * 4);
            }
        }

#pragma unroll
        for (int kk = 0; kk < 2; ++kk) {
#pragma unroll
            for (int mt = 0; mt < 2; ++mt) {
                uint32_t ah[4], al[4];
                const int arow = am0 + mt * 16 + (lane & 15);
                const int acol = kk * 16 + (lane >> 4) * 8;
                ldsm4(ah, &sAhi[arow * 40 + acol]);
                ldsm4(al, &sAlo[arow * 40 + acol]);
#pragma unroll
                for (int nt = 0; nt < 4; ++nt) {
                    uint32_t bh[4], bl[4];
                    const int boff = (kk * 16 + (lane & 15)) * 136 + cn0 +
                                     nt * 16 + (lane >> 4) * 8;
                    ldsm4t(bh, &sWhi[boff]);
                    ldsm4t(bl, &sWlo[boff]);
                    float* c0 = cf[mt * 8 + nt * 2];
                    float* c1 = cf[mt * 8 + nt * 2 + 1];
                    mma16816(c0, ah, bh[0], bh[1]);
                    mma16816(c1, ah, bh[2], bh[3]);
                    mma16816(c0, ah, bl[0], bl[1]);
                    mma16816(c1, ah, bl[2], bl[3]);
                    mma16816(c0, al, bh[0], bh[1]);
                    mma16816(c1, al, bh[2], bh[3]);
                }
            }
        }
        __syncthreads();
    }

    const int rlo = am0 + (lane >> 2);
#pragma unroll
    for (int mt = 0; mt < 2; ++mt) {
#pragma unroll
        for (int j = 0; j < 8; ++j) {
            int nt = j >> 1;
            int half8 = j & 1;
            float* cc = cf[mt * 8 + j];
            int row = rlo + mt * 16;
            int col = nc0 + cn0 + nt * 16 + half8 * 8 + (lane & 3) * 2;
            {
                float x = cc[0], y = cc[1];
                __half2 hi = __floats2half2_rn(x, y);
                __half2 lo = __floats2half2_rn(x - __low2float(hi), y - __high2float(hi));
                size_t off = (size_t)(m0 + row) * 256 + col;
                *(__half2*)&Chi[off] = hi;
                *(__half2*)&Clo[off] = lo;
            }
            {
                float x = cc[2], y = cc[3];
                __half2 hi = __floats2half2_rn(x, y);
                __half2 lo = __floats2half2_rn(x - __low2float(hi), y - __high2float(hi));
                size_t off = (size_t)(m0 + row + 8) * 256 + col;
                *(__half2*)&Chi[off] = hi;
                *(__half2*)&Clo[off] = lo;
            }
        }
    }
}

// ---------------------------------------------------------------------------
// Merged triple dot over both h tensors
// ---------------------------------------------------------------------------
__global__ __launch_bounds__(256) void edot_all(
    const float* __restrict__ a1_0, const float* __restrict__ a2_0,
    const float* __restrict__ a1_1, const float* __restrict__ a2_1)
{
    const int gr = blockIdx.x * 8 + (threadIdx.x >> 5);
    const int lane = threadIdx.x & 31;
    const __half *ph, *pl;
    const float *v0, *v1, *v2;
    float *e0, *e1, *e2;
    int r;
    if (gr < BATCH * N1) {
        r = gr;
        ph = g_h0hi + (size_t)r * 256; pl = g_h0lo + (size_t)r * 256;
        v0 = a1_0; v1 = a2_0; v2 = a2_1;
        e0 = g_eA; e1 = g_eB; e2 = g_eE;
    } else {
        r = gr - BATCH * N1;
        ph = g_h1hi + (size_t)r * 256; pl = g_h1lo + (size_t)r * 256;
        v0 = a2_0; v1 = a1_1; v2 = a2_1;
        e0 = g_eC; e1 = g_eD; e2 = g_eF;
    }
    float s0 = 0.f, s1 = 0.f, s2 = 0.f;
#pragma unroll
    for (int i = 0; i < 8; ++i) {
        int c = lane + i * 32;
        float x = __half2float(ph[c]) + __half2float(pl[c]);
        s0 += x * v0[c];
        s1 += x * v1[c];
        s2 += x * v2[c];
    }
#pragma unroll
    for (int o = 16; o > 0; o >>= 1) {
        s0 += __shfl_xor_sync(0xffffffffu, s0, o);
        s1 += __shfl_xor_sync(0xffffffffu, s1, o);
        s2 += __shfl_xor_sync(0xffffffffu, s2, o);
    }
    if (lane == 0) { e0[r] = s0; e1[r] = s1; e2[r] = s2; }
}

// Merged per-batch max over the 4 e2 vectors
__global__ __launch_bounds__(256) void bmax_all()
{
    __shared__ float red[256];
    const int blk = blockIdx.x >> 6;
    const int b   = blockIdx.x & 63;
    const int t   = threadIdx.x;
    const float* p;
    int M;
    if (blk == 0)      { p = g_eB; M = N1; }
    else if (blk == 1) { p = g_eC; M = N2; }
    else if (blk == 2) { p = g_eE; M = N1; }
    else               { p = g_eF; M = N2; }
    p += (size_t)b * M;
    float m = -3.4e38f;
    for (int i = t; i < M; i += 256) m = fmaxf(m, p[i]);
    red[t] = m;
    __syncthreads();
    for (int s = 128; s > 0; s >>= 1) {
        if (t < s) red[t] = fmaxf(red[t], red[t + s]);
        __syncthreads();
    }
    if (t == 0) g_mx[blk * BATCH + b] = red[0];
}

// Merged P2/Q2 kernel over the 4 segments
__global__ __launch_bounds__(256) void pq_all()
{
    const int bx = blockIdx.x;   // [0,12)
    const int b  = blockIdx.y;
    const float* e2; int M, mxi; size_t off; int i0;
    if (bx < 4)       { e2 = g_eB; M = N1; mxi = 0; off = PQ_O0; i0 = bx * 256; }
    else if (bx < 6)  { e2 = g_eC; M = N2; mxi = 1; off = PQ_O1; i0 = (bx - 4) * 256; }
    else if (bx < 10) { e2 = g_eE; M = N1; mxi = 2; off = PQ_O2; i0 = (bx - 6) * 256; }
    else              { e2 = g_eF; M = N2; mxi = 3; off = PQ_O3; i0 = (bx - 10) * 256; }
    const int i = i0 + threadIdx.x;
    float d = e2[(size_t)b * M + i] - g_mx[mxi * BATCH + b];
    g_P2[off + (size_t)b * M + i] = __expf(d);
    g_Q2[off + (size_t)b * M + i] = __expf(0.2f * d);
}

// ---------------------------------------------------------------------------
// Merged fused masked attention (all 4 blocks), software-pipelined.
// Warp mapping: 2 m-groups x 4 n-groups (B fragments reused across 2 m-tiles)
// ---------------------------------------------------------------------------
__global__ __launch_bounds__(256, 2) void att_all(
    const int* __restrict__ adj00, const int* __restrict__ adj01,
    const int* __restrict__ adj10, const int* __restrict__ adj11,
    const float* __restrict__ bias, float* __restrict__ out)
{
    __shared__ __align__(16) __half sW[2][64 * 40];
    __shared__ __align__(16) __half sB[2][32 * 264];
    __shared__ float sP1[64], sQ1[64], sSum[64], sDeg[64];

    const int bx = blockIdx.x;   // [0,48): 16 blk00 | 8 blk10 | 16 blk01 | 8 blk11
    const int b  = blockIdx.y;
    const __half* g; const int* adjB; const float* e1B;
    int mxi, N, M, tl; size_t pqo, oof;
    if (bx < 16) {
        tl = bx;      g = g_h0hi; adjB = adj00; e1B = g_eA; mxi = 0;
        pqo = PQ_O0; oof = OO_00; N = N1; M = N1;
    } else if (bx < 24) {
        tl = bx - 16; g = g_h0hi; adjB = adj10; e1B = g_eD; mxi = 2;
        pqo = PQ_O2; oof = OO_10; N = N2; M = N1;
    } else if (bx < 40) {
        tl = bx - 24; g = g_h1hi; adjB = adj01; e1B = g_eA; mxi = 1;
        pqo = PQ_O1; oof = OO_01; N = N1; M = N2;
    } else {
        tl = bx - 40; g = g_h1hi; adjB = adj11; e1B = g_eD; mxi = 3;
        pqo = PQ_O3; oof = OO_11; N = N2; M = N2;
    }
    const int n0 = tl * 64;

    const int t    = threadIdx.x;
    const int lane = t & 31;
    const int wid  = t >> 5;

    if (t < 64) {
        float v = e1B[(size_t)b * N + n0 + t] + g_mx[mxi * BATCH + b];
        float sh = fmaxf(v, 0.2f * v);
        sP1[t] = __expf(v - sh);
        sQ1[t] = __expf(0.2f * v - sh);
        sSum[t] = 0.f;
        sDeg[t] = 0.f;
    }
    __syncthreads();

    float c[16][4];
#pragma unroll
    for (int i = 0; i < 16; ++i)
#pragma unroll
        for (int j = 0; j < 4; ++j) c[i][j] = 0.f;

    // g tile cp.async: row k = t>>3, cols (t&7)*32 .. +31
    const int bk = t >> 3;
    const int bc = (t & 7) * 32;
    const __half* gsrc = g + ((size_t)b * M + bk) * 256 + bc;
    const uint32_t sb0 = (uint32_t)__cvta_generic_to_shared(&sB[0][bk * 264 + bc]);
    const uint32_t sb1 = (uint32_t)__cvta_generic_to_shared(&sB[1][bk * 264 + bc]);

    // w-gen: row r = t>>2, cols (t&3)*8 .. +7
    const int wr = t >> 2;
    const int wc = (t & 3) * 8;
    const int* adjp = adjB + ((size_t)b * N + n0 + wr) * M + wc;
    const float* p2p = g_P2 + pqo + (size_t)b * M + wc;
    const float* q2p = g_Q2 + pqo + (size_t)b * M + wc;
    const float P1r = sP1[wr];
    const float Q1r = sQ1[wr];

    // MMA mapping: warp = (wid&1) m-group (32 rows) x (wid>>1) n-group (64 cols)
    const int mgrp = (wid & 1) * 32;
    const int ngrp = (wid >> 1) * 64;
    const int aOff0 = (mgrp + (lane & 15)) * 40 + (lane >> 4) * 8;
    const int aOff1 = aOff0 + 16 * 40;
    const int bRowOff = (lane & 15) * 264 + ngrp + (lane >> 4) * 8;

    const int iters = M >> 5;

    // ---- prolog: stage chunk 0 ----
    {
#pragma unroll
        for (int j = 0; j < 4; ++j) cp16(sb0 + j * 16, gsrc + j * 8);
        CP_COMMIT();
        int4 a0 = *(const int4*)(adjp);
        int4 a1 = *(const int4*)(adjp + 4);
        float4 p0 = *(const float4*)(p2p);
        float4 p1 = *(const float4*)(p2p + 4);
        float4 q0 = *(const float4*)(q2p);
        float4 q1 = *(const float4*)(q2p + 4);
        W8 w = wgen8(a0, a1, p0, p1, q0, q1, P1r, Q1r);
        *(uint4*)&sW[0][wr * 40 + wc] = w.v;
        float ssum = w.ssum, cnt = w.cnt;
        ssum += __shfl_xor_sync(0xffffffffu, ssum, 1);
        ssum += __shfl_xor_sync(0xffffffffu, ssum, 2);
        cnt  += __shfl_xor_sync(0xffffffffu, cnt, 1);
        cnt  += __shfl_xor_sync(0xffffffffu, cnt, 2);
        if ((t & 3) == 0) { sSum[wr] += ssum; sDeg[wr] += cnt; }
        CP_WAIT0();
    }
    __syncthreads();

    for (int it = 0; it < iters; ++it) {
        const int cur = it & 1;
        const bool hasNext = (it + 1) < iters;
        int4 a0, a1; float4 p0, p1, q0, q1;

        if (hasNext) {
            const int m1 = (it + 1) * 32;
            const uint32_t sbn = (cur ^ 1) ? sb1 : sb0;
#pragma unroll
            for (int j = 0; j < 4; ++j)
                cp16(sbn + j * 16, gsrc + (size_t)m1 * 256 + j * 8);
            CP_COMMIT();
            a0 = *(const int4*)(adjp + m1);
            a1 = *(const int4*)(adjp + m1 + 4);
            p0 = *(const float4*)(p2p + m1);
            p1 = *(const float4*)(p2p + m1 + 4);
            q0 = *(const float4*)(q2p + m1);
            q1 = *(const float4*)(q2p + m1 + 4);
        }

        // ---- MMA from buffer cur: 2 m-tiles share each B fragment ----
        {
            const __half* wbase = &sW[cur][0];
            const __half* bbase = &sB[cur][0];
#pragma unroll
            for (int kk = 0; kk < 2; ++kk) {
                uint32_t af0[4], af1[4];
                ldsm4(af0, wbase + aOff0 + kk * 16);
                ldsm4(af1, wbase + aOff1 + kk * 16);
#pragma unroll
                for (int nb = 0; nb < 4; ++nb) {
                    uint32_t bh[4];
                    ldsm4t(bh, bbase + kk * 16 * 264 + bRowOff + nb * 16);
                    mma16816(c[nb * 2],     af0, bh[0], bh[1]);
                    mma16816(c[nb * 2 + 1], af0, bh[2], bh[3]);
                    mma16816(c[8 + nb * 2],     af1, bh[0], bh[1]);
                    mma16816(c[8 + nb * 2 + 1], af1, bh[2], bh[3]);
                }
            }
        }

        if (hasNext) {
            W8 w = wgen8(a0, a1, p0, p1, q0, q1, P1r, Q1r);
            *(uint4*)&sW[cur ^ 1][wr * 40 + wc] = w.v;
            float ssum = w.ssum, cnt = w.cnt;
            ssum += __shfl_xor_sync(0xffffffffu, ssum, 1);
            ssum += __shfl_xor_sync(0xffffffffu, ssum, 2);
            cnt  += __shfl_xor_sync(0xffffffffu, cnt, 1);
            cnt  += __shfl_xor_sync(0xffffffffu, cnt, 2);
            if ((t & 3) == 0) { sSum[wr] += ssum; sDeg[wr] += cnt; }
            CP_WAIT0();
        }
        __syncthreads();
    }

    // ---- epilogue ----
    float* ob = out + oof;
#pragma unroll
    for (int mt = 0; mt < 2; ++mt) {
        const int rlo = mgrp + mt * 16 + (lane >> 2);
        const int rhi = rlo + 8;
        float slo = (sDeg[rlo] > 0.f && sSum[rlo] > 0.f) ? sDeg[rlo] / sSum[rlo] : 0.f;
        float shi = (sDeg[rhi] > 0.f && sSum[rhi] > 0.f) ? sDeg[rhi] / sSum[rhi] : 0.f;
        float* olo = ob + ((size_t)b * N + n0 + rlo) * 256;
        float* ohi = ob + ((size_t)b * N + n0 + rhi) * 256;
#pragma unroll
        for (int j = 0; j < 8; ++j) {
            int nt = j >> 1;
            int half8 = j & 1;
            float* cc = c[mt * 8 + j];
            int col = ngrp + nt * 16 + half8 * 8 + (lane & 3) * 2;
            float b0 = bias[col], b1 = bias[col + 1];
            float2 v0 = make_float2(cc[0] * slo + b0, cc[1] * slo + b1);
            float2 v1 = make_float2(cc[2] * shi + b0, cc[3] * shi + b1);
            *(float2*)(olo + col) = v0;
            *(float2*)(ohi + col) = v1;
        }
    }
}

// ---------------------------------------------------------------------------
// Launch: 5 kernels total
// ---------------------------------------------------------------------------
extern "C" void kernel_launch(void* const* d_in, const int* in_sizes, int n_in,
                              void* d_out, int out_size)
{
    const float* x0   = (const float*)d_in[0];
    const float* x1   = (const float*)d_in[1];
    const float* W0   = (const float*)d_in[2];
    const float* W1   = (const float*)d_in[3];
    const float* a1_0 = (const float*)d_in[4];
    const float* a2_0 = (const float*)d_in[5];
    const float* a1_1 = (const float*)d_in[6];
    const float* a2_1 = (const float*)d_in[7];
    const float* bias = (const float*)d_in[8];
    const int* adj00  = (const int*)d_in[9];
    const int* adj01  = (const int*)d_in[10];
    const int* adj10  = (const int*)d_in[11];
    const int* adj11  = (const int*)d_in[12];
    float* out = (float*)d_out;

    const int R0 = BATCH * N1;   // 65536
    const int R1 = BATCH * N2;   // 32768

    gemm_all<<<dim3((R0 + R1) / 128, 2), 256>>>(x0, x1, W0, W1);
    edot_all<<<(R0 + R1) / 8, 256>>>(a1_0, a2_0, a1_1, a2_1);
    bmax_all<<<4 * BATCH, 256>>>();
    pq_all<<<dim3(12, BATCH), 256>>>();
    att_all<<<dim3(48, BATCH), 256>>>(adj00, adj01, adj10, adj11, bias, out);
}